// round 1
// baseline (speedup 1.0000x reference)
#include <cuda_runtime.h>
#include <math.h>

// ---------------- problem constants ----------------
#define BB     16
#define HH     112
#define WWID   112
#define CC     96
#define NHEADS 3
#define HD     32
#define WS     7
#define NWIN   49          // tokens per window
#define SHIFT  3
#define NW_IMG 256         // windows per image (16x16)
#define M_TOK  200704      // B * H * W
#define HID_D  384

// ---------------- scratch (static device memory; no allocs allowed) --------
__device__ float g_xw [(size_t)M_TOK * CC];      // LN1 + shift + window partition
__device__ float g_qkv[(size_t)M_TOK * 3 * CC];  // qkv projection
__device__ float g_att[(size_t)M_TOK * CC];      // attention output (window layout)
__device__ float g_x1 [(size_t)M_TOK * CC];      // residual 1 ((B,L,C) layout)
__device__ float g_y  [(size_t)M_TOK * CC];      // LN2 output
__device__ float g_h1 [(size_t)M_TOK * HID_D];   // fc1+gelu output

// ---------------- LayerNorm (warp per token) ----------------
// MODE 0: read x with shift+window-partition gather, write window layout
// MODE 1: plain (B,L,C) -> (B,L,C)
template<int MODE>
__global__ __launch_bounds__(256)
void ln_kernel(const float* __restrict__ x, const float* __restrict__ g,
               const float* __restrict__ beta, float* __restrict__ out)
{
    int t    = (blockIdx.x * blockDim.x + threadIdx.x) >> 5;
    int lane = threadIdx.x & 31;
    if (t >= M_TOK) return;

    const float* src;
    if (MODE == 0) {
        int win = t / NWIN, n = t % NWIN;
        int b  = win >> 8;         // win / 256
        int wi = win & 255;
        int wh = wi >> 4, ww = wi & 15;
        int i = n / WS, j = n % WS;
        int r = wh * WS + i + SHIFT; if (r >= HH)   r -= HH;
        int c = ww * WS + j + SHIFT; if (c >= WWID) c -= WWID;
        src = x + ((size_t)b * (HH * WWID) + r * WWID + c) * CC;
    } else {
        src = x + (size_t)t * CC;
    }

    float v0 = src[lane], v1 = src[lane + 32], v2 = src[lane + 64];
    float s = v0 + v1 + v2;
    #pragma unroll
    for (int o = 16; o; o >>= 1) s += __shfl_xor_sync(0xffffffffu, s, o);
    float mean = s * (1.0f / 96.0f);
    float d0 = v0 - mean, d1 = v1 - mean, d2 = v2 - mean;
    float q = d0 * d0 + d1 * d1 + d2 * d2;
    #pragma unroll
    for (int o = 16; o; o >>= 1) q += __shfl_xor_sync(0xffffffffu, q, o);
    float rstd = rsqrtf(q * (1.0f / 96.0f) + 1e-5f);

    float* dst = out + (size_t)t * CC;
    dst[lane]      = d0 * rstd * g[lane]      + beta[lane];
    dst[lane + 32] = d1 * rstd * g[lane + 32] + beta[lane + 32];
    dst[lane + 64] = d2 * rstd * g[lane + 64] + beta[lane + 64];
}

// ---------------- generic tiled fp32 GEMM:  out = A(MxK) * W(NxK)^T + bias --
// EPI 0: plain bias
// EPI 1: bias + exact GELU
// EPI 2: bias + window-reverse scatter + residual (res = original x), N must be 96
// EPI 3: bias + residual (same layout), N must be 96
#define BM 128
#define BN 32
#define BK 32

template<int EPI>
__global__ __launch_bounds__(256)
void gemm_kernel(const float* __restrict__ A, const float* __restrict__ W,
                 const float* __restrict__ bias, float* __restrict__ out,
                 const float* __restrict__ res, int K, int N)
{
    __shared__ float As[BM][BK + 4];   // row-major, padded for bank-free column reads
    __shared__ float Ws[BK][BN + 1];   // transposed: Ws[k][n]

    int m0  = blockIdx.x * BM;
    int n0  = blockIdx.y * BN;
    int tid = threadIdx.x;
    int rowbase = (tid >> 4) * 8;      // 16 row-groups of 8
    int colbase = (tid & 15) * 2;      // 16 col-groups of 2

    float acc[8][2];
    #pragma unroll
    for (int i = 0; i < 8; i++) { acc[i][0] = 0.f; acc[i][1] = 0.f; }

    int ktiles = K >> 5;
    for (int kt = 0; kt < ktiles; kt++) {
        // load A tile (128 x 32) with float4
        #pragma unroll
        for (int i = 0; i < 4; i++) {
            int fid = tid + i * 256;
            int row = fid >> 3, k4 = (fid & 7) << 2;
            float4 av = *(const float4*)(A + (size_t)(m0 + row) * K + kt * BK + k4);
            *(float4*)&As[row][k4] = av;
        }
        // load W tile (32 x 32), store transposed
        {
            int row = tid >> 3, k4 = (tid & 7) << 2;
            float4 wv = *(const float4*)(W + (size_t)(n0 + row) * K + kt * BK + k4);
            Ws[k4 + 0][row] = wv.x; Ws[k4 + 1][row] = wv.y;
            Ws[k4 + 2][row] = wv.z; Ws[k4 + 3][row] = wv.w;
        }
        __syncthreads();
        #pragma unroll
        for (int kk = 0; kk < BK; kk++) {
            float b0 = Ws[kk][colbase], b1 = Ws[kk][colbase + 1];
            #pragma unroll
            for (int i = 0; i < 8; i++) {
                float a = As[rowbase + i][kk];
                acc[i][0] += a * b0;
                acc[i][1] += a * b1;
            }
        }
        __syncthreads();
    }

    #pragma unroll
    for (int i = 0; i < 8; i++) {
        int m = m0 + rowbase + i;
        #pragma unroll
        for (int j = 0; j < 2; j++) {
            int n = n0 + colbase + j;
            float v = acc[i][j] + bias[n];
            if (EPI == 0) {
                out[(size_t)m * N + n] = v;
            } else if (EPI == 1) {
                out[(size_t)m * N + n] = 0.5f * v * (1.0f + erff(v * 0.70710678118654752f));
            } else if (EPI == 2) {
                int win = m / NWIN, nn = m % NWIN;
                int b  = win >> 8;
                int wi = win & 255;
                int wh = wi >> 4, ww = wi & 15;
                int ii = nn / WS, jj = nn % WS;
                int r = wh * WS + ii + SHIFT; if (r >= HH)   r -= HH;
                int c = ww * WS + jj + SHIFT; if (c >= WWID) c -= WWID;
                size_t dst = ((size_t)b * (HH * WWID) + r * WWID + c) * CC + n;
                out[dst] = res[dst] + v;
            } else {  // EPI == 3
                size_t dst = (size_t)m * CC + n;
                out[dst] = res[dst] + v;
            }
        }
    }
}

// ---------------- fused window attention: one block per (window, head) -----
__global__ __launch_bounds__(128)
void attn_kernel(const float* __restrict__ qkv, const float* __restrict__ mask,
                 const float* __restrict__ relb, float* __restrict__ out)
{
    int win = blockIdx.x;
    int h   = blockIdx.y;
    int tid = threadIdx.x;

    __shared__ float q[NWIN][HD];
    __shared__ float k[NWIN][HD];
    __shared__ float v[NWIN][HD];
    __shared__ float s[NWIN][NWIN + 1];

    const float* base = qkv + (size_t)win * NWIN * (3 * CC) + h * HD;
    for (int p = tid; p < NWIN * HD; p += 128) {
        int n = p >> 5, d = p & 31;
        q[n][d] = base[(size_t)n * (3 * CC) + d];
        k[n][d] = base[(size_t)n * (3 * CC) + CC + d];
        v[n][d] = base[(size_t)n * (3 * CC) + 2 * CC + d];
    }
    __syncthreads();

    int wi = win & 255;
    const float* mwin = mask + (size_t)wi * NWIN * NWIN;
    for (int p = tid; p < NWIN * NWIN; p += 128) {
        int n = p / NWIN, m = p % NWIN;
        float acc = 0.f;
        #pragma unroll
        for (int d = 0; d < HD; d++) acc += q[n][d] * k[m][d];
        int i1 = n / WS, j1 = n % WS, i2 = m / WS, j2 = m % WS;
        int ridx = (i1 - i2 + WS - 1) * (2 * WS - 1) + (j1 - j2 + WS - 1);
        s[n][m] = acc * 0.17677669529663689f + relb[ridx * NHEADS + h] + mwin[p];
    }
    __syncthreads();

    if (tid < NWIN) {
        int n = tid;
        float mx = -1e30f;
        for (int m = 0; m < NWIN; m++) mx = fmaxf(mx, s[n][m]);
        float sum = 0.f;
        for (int m = 0; m < NWIN; m++) { float e = __expf(s[n][m] - mx); s[n][m] = e; sum += e; }
        float inv = 1.0f / sum;
        for (int m = 0; m < NWIN; m++) s[n][m] *= inv;
    }
    __syncthreads();

    for (int p = tid; p < NWIN * HD; p += 128) {
        int n = p >> 5, d = p & 31;
        float acc = 0.f;
        #pragma unroll
        for (int m = 0; m < NWIN; m++) acc += s[n][m] * v[m][d];
        out[((size_t)win * NWIN + n) * CC + h * HD + d] = acc;
    }
}

// ---------------- launch ----------------
extern "C" void kernel_launch(void* const* d_in, const int* in_sizes, int n_in,
                              void* d_out, int out_size)
{
    const float* x      = (const float*)d_in[0];
    const float* mask   = (const float*)d_in[1];
    const float* n1g    = (const float*)d_in[2];
    const float* n1b    = (const float*)d_in[3];
    const float* qkv_w  = (const float*)d_in[4];
    const float* qkv_b  = (const float*)d_in[5];
    const float* relb   = (const float*)d_in[6];
    const float* proj_w = (const float*)d_in[7];
    const float* proj_b = (const float*)d_in[8];
    const float* n2g    = (const float*)d_in[9];
    const float* n2b    = (const float*)d_in[10];
    const float* fc1_w  = (const float*)d_in[11];
    const float* fc1_b  = (const float*)d_in[12];
    const float* fc2_w  = (const float*)d_in[13];
    const float* fc2_b  = (const float*)d_in[14];
    float* out = (float*)d_out;

    float *xw, *qkvb, *att, *x1, *y, *h1;
    cudaGetSymbolAddress((void**)&xw,   g_xw);
    cudaGetSymbolAddress((void**)&qkvb, g_qkv);
    cudaGetSymbolAddress((void**)&att,  g_att);
    cudaGetSymbolAddress((void**)&x1,   g_x1);
    cudaGetSymbolAddress((void**)&y,    g_y);
    cudaGetSymbolAddress((void**)&h1,   g_h1);

    const int LN_BLOCKS = M_TOK / 8;    // 8 warps (tokens) per 256-thread block
    const int GM = M_TOK / BM;          // 1568

    // 1) LN1 + shift + window partition
    ln_kernel<0><<<LN_BLOCKS, 256>>>(x, n1g, n1b, xw);
    // 2) QKV projection: (M x 96) * (288 x 96)^T
    gemm_kernel<0><<<dim3(GM, 3 * CC / BN), 256>>>(xw, qkv_w, qkv_b, qkvb, nullptr, CC, 3 * CC);
    // 3) fused window attention
    attn_kernel<<<dim3(BB * NW_IMG, NHEADS), 128>>>(qkvb, mask, relb, att);
    // 4) proj + window reverse + unshift + residual -> x1 (B,L,C)
    gemm_kernel<2><<<dim3(GM, CC / BN), 256>>>(att, proj_w, proj_b, x1, x, CC, CC);
    // 5) LN2
    ln_kernel<1><<<LN_BLOCKS, 256>>>(x1, n2g, n2b, y);
    // 6) FC1 + GELU
    gemm_kernel<1><<<dim3(GM, HID_D / BN), 256>>>(y, fc1_w, fc1_b, h1, nullptr, CC, HID_D);
    // 7) FC2 + residual -> out
    gemm_kernel<3><<<dim3(GM, CC / BN), 256>>>(h1, fc2_w, fc2_b, out, x1, HID_D, CC);
}

// round 3
// speedup vs baseline: 2.2434x; 2.2434x over previous
#include <cuda_runtime.h>
#include <math.h>
#include <stdint.h>

// ---------------- problem constants ----------------
#define BB     16
#define HH     112
#define WWID   112
#define CC     96
#define NHEADS 3
#define HD     32
#define WS     7
#define NWIN   49
#define SHIFT  3
#define NW_IMG 256
#define M_TOK  200704
#define HID_D  384

// ---------------- scratch ----------------
__device__ float g_xw [(size_t)M_TOK * CC];
__device__ float g_qkv[(size_t)M_TOK * 3 * CC];
__device__ float g_att[(size_t)M_TOK * CC];
__device__ float g_x1 [(size_t)M_TOK * CC];
__device__ float g_y  [(size_t)M_TOK * CC];
__device__ float g_h1 [(size_t)M_TOK * HID_D];

// ---------------- tf32 helpers ----------------
__device__ __forceinline__ float to_tf32(float x) {
    uint32_t u;
    asm("cvt.rna.tf32.f32 %0, %1;" : "=r"(u) : "f"(x));
    return __uint_as_float(u);
}

// m16n8k8 tf32 mma. PTX ISA fragment layout (each reg = 1 elem):
//  A: a0=(g,t) a1=(g+8,t) a2=(g,t+4) a3=(g+8,t+4)
//  B: b0=(k=t,n=g) b1=(k=t+4,n=g)
//  C: c0=(g,2t) c1=(g,2t+1) c2=(g+8,2t) c3=(g+8,2t+1)
__device__ __forceinline__ void mma_tf32(float* c, float a0, float a1,
                                         float a2, float a3,
                                         float b0, float b1) {
    asm volatile(
        "mma.sync.aligned.m16n8k8.row.col.f32.tf32.tf32.f32 "
        "{%0,%1,%2,%3}, {%4,%5,%6,%7}, {%8,%9}, {%0,%1,%2,%3};"
        : "+f"(c[0]), "+f"(c[1]), "+f"(c[2]), "+f"(c[3])
        : "r"(__float_as_uint(a0)), "r"(__float_as_uint(a1)),
          "r"(__float_as_uint(a2)), "r"(__float_as_uint(a3)),
          "r"(__float_as_uint(b0)), "r"(__float_as_uint(b1)));
}

// ---------------- LayerNorm (warp per token) ----------------
template<int MODE>
__global__ __launch_bounds__(256)
void ln_kernel(const float* __restrict__ x, const float* __restrict__ g,
               const float* __restrict__ beta, float* __restrict__ out)
{
    int t    = (blockIdx.x * blockDim.x + threadIdx.x) >> 5;
    int lane = threadIdx.x & 31;
    if (t >= M_TOK) return;

    const float* src;
    if (MODE == 0) {
        int win = t / NWIN, n = t % NWIN;
        int b  = win >> 8;
        int wi = win & 255;
        int wh = wi >> 4, ww = wi & 15;
        int i = n / WS, j = n % WS;
        int r = wh * WS + i + SHIFT; if (r >= HH)   r -= HH;
        int c = ww * WS + j + SHIFT; if (c >= WWID) c -= WWID;
        src = x + ((size_t)b * (HH * WWID) + r * WWID + c) * CC;
    } else {
        src = x + (size_t)t * CC;
    }

    float v0 = src[lane], v1 = src[lane + 32], v2 = src[lane + 64];
    float s = v0 + v1 + v2;
    #pragma unroll
    for (int o = 16; o; o >>= 1) s += __shfl_xor_sync(0xffffffffu, s, o);
    float mean = s * (1.0f / 96.0f);
    float d0 = v0 - mean, d1 = v1 - mean, d2 = v2 - mean;
    float q = d0 * d0 + d1 * d1 + d2 * d2;
    #pragma unroll
    for (int o = 16; o; o >>= 1) q += __shfl_xor_sync(0xffffffffu, q, o);
    float rstd = rsqrtf(q * (1.0f / 96.0f) + 1e-5f);

    float* dst = out + (size_t)t * CC;
    dst[lane]      = d0 * rstd * g[lane]      + beta[lane];
    dst[lane + 32] = d1 * rstd * g[lane + 32] + beta[lane + 32];
    dst[lane + 64] = d2 * rstd * g[lane + 64] + beta[lane + 64];
}

// ---------------- tensor-core GEMM: out = A(MxK) * W(NxK)^T + bias ---------
// BM=128, BN=96, BK=32, 384 threads (12 warps: 4m x 3n), warp = 32x32
template<int EPI>
__global__ __launch_bounds__(384)
void gemm_tc(const float* __restrict__ A, const float* __restrict__ W,
             const float* __restrict__ bias, float* __restrict__ out,
             const float* __restrict__ res, int K, int N)
{
    __shared__ float As[128][36];
    __shared__ float Ws[96][36];

    int tid  = threadIdx.x;
    int wid  = tid >> 5, lane = tid & 31;
    int g    = lane >> 2, t = lane & 3;
    int wm   = wid & 3, wn = wid >> 2;
    int m0   = blockIdx.x * 128, n0 = blockIdx.y * 96;

    float c[2][4][4];
    #pragma unroll
    for (int i = 0; i < 2; i++)
        #pragma unroll
        for (int j = 0; j < 4; j++)
            #pragma unroll
            for (int l = 0; l < 4; l++) c[i][j][l] = 0.f;

    for (int kt = 0; kt < K; kt += 32) {
        for (int idx = tid; idx < 128 * 8; idx += 384) {
            int row = idx >> 3, c4 = (idx & 7) << 2;
            float4 v = *(const float4*)(A + (size_t)(m0 + row) * K + kt + c4);
            As[row][c4 + 0] = to_tf32(v.x);
            As[row][c4 + 1] = to_tf32(v.y);
            As[row][c4 + 2] = to_tf32(v.z);
            As[row][c4 + 3] = to_tf32(v.w);
        }
        for (int idx = tid; idx < 96 * 8; idx += 384) {
            int row = idx >> 3, c4 = (idx & 7) << 2;
            float4 v = *(const float4*)(W + (size_t)(n0 + row) * K + kt + c4);
            Ws[row][c4 + 0] = to_tf32(v.x);
            Ws[row][c4 + 1] = to_tf32(v.y);
            Ws[row][c4 + 2] = to_tf32(v.z);
            Ws[row][c4 + 3] = to_tf32(v.w);
        }
        __syncthreads();

        #pragma unroll
        for (int ks = 0; ks < 4; ks++) {
            int kc = ks * 8 + t;
            float a[2][4];
            #pragma unroll
            for (int mt = 0; mt < 2; mt++) {
                int r = wm * 32 + mt * 16 + g;
                a[mt][0] = As[r][kc];
                a[mt][1] = As[r + 8][kc];
                a[mt][2] = As[r][kc + 4];
                a[mt][3] = As[r + 8][kc + 4];
            }
            #pragma unroll
            for (int nt = 0; nt < 4; nt++) {
                int nr = wn * 32 + nt * 8 + g;
                float b0 = Ws[nr][kc], b1 = Ws[nr][kc + 4];
                #pragma unroll
                for (int mt = 0; mt < 2; mt++)
                    mma_tf32(c[mt][nt], a[mt][0], a[mt][1], a[mt][2], a[mt][3], b0, b1);
            }
        }
        __syncthreads();
    }

    #pragma unroll
    for (int mt = 0; mt < 2; mt++) {
        #pragma unroll
        for (int rh = 0; rh < 2; rh++) {
            int m = m0 + wm * 32 + mt * 16 + g + rh * 8;
            size_t rowbase;
            if (EPI == 2) {
                int win = m / NWIN, nn = m % NWIN;
                int b  = win >> 8;
                int wi = win & 255;
                int wh = wi >> 4, ww = wi & 15;
                int ii = nn / WS, jj = nn % WS;
                int r = wh * WS + ii + SHIFT; if (r >= HH)   r -= HH;
                int ccol = ww * WS + jj + SHIFT; if (ccol >= WWID) ccol -= WWID;
                rowbase = ((size_t)b * (HH * WWID) + r * WWID + ccol) * CC;
            } else {
                rowbase = (size_t)m * N;
            }
            #pragma unroll
            for (int nt = 0; nt < 4; nt++) {
                #pragma unroll
                for (int j = 0; j < 2; j++) {
                    int n = n0 + wn * 32 + nt * 8 + 2 * t + j;
                    float v = c[mt][nt][rh * 2 + j] + bias[n];
                    if (EPI == 0) {
                        out[rowbase + n] = v;
                    } else if (EPI == 1) {
                        out[rowbase + n] = 0.5f * v * (1.0f + erff(v * 0.70710678118654752f));
                    } else {
                        out[rowbase + n] = res[rowbase + n] + v;
                    }
                }
            }
        }
    }
}

// ---------------- tensor-core window attention (block per window) ----------
__global__ __launch_bounds__(128)
void attn_tc(const float* __restrict__ qkv, const float* __restrict__ mask,
             const float* __restrict__ relb, float* __restrict__ out)
{
    __shared__ float qs[64][36];   // queries, rows padded to 64
    __shared__ float ks_[56][36];  // keys, rows padded to 56
    __shared__ float vt[32][60];   // V transposed: vt[d][key]
    __shared__ float ss[64][60];   // scores / probs

    int win  = blockIdx.x;
    int tid  = threadIdx.x;
    int wid  = tid >> 5, lane = tid & 31;
    int g    = lane >> 2, t = lane & 3;
    const float scale = 0.17677669529663689f;

    const float* mwin = mask + (size_t)(win & 255) * (NWIN * NWIN);
    const float* base = qkv + (size_t)win * NWIN * (3 * CC);

    for (int h = 0; h < NHEADS; h++) {
        for (int p = tid; p < 64 * HD; p += 128) {
            int n = p >> 5, d = p & 31;
            float v = (n < NWIN) ? base[(size_t)n * (3 * CC) + h * HD + d] : 0.f;
            qs[n][d] = to_tf32(v);
        }
        for (int p = tid; p < 56 * HD; p += 128) {
            int n = p >> 5, d = p & 31;
            float kv = (n < NWIN) ? base[(size_t)n * (3 * CC) + CC + h * HD + d] : 0.f;
            float vv = (n < NWIN) ? base[(size_t)n * (3 * CC) + 2 * CC + h * HD + d] : 0.f;
            ks_[n][d] = to_tf32(kv);
            vt[d][n]  = to_tf32(vv);
        }
        __syncthreads();

        // ---- S = Q K^T ----
        float sc[7][4];
        #pragma unroll
        for (int nt = 0; nt < 7; nt++)
            #pragma unroll
            for (int l = 0; l < 4; l++) sc[nt][l] = 0.f;

        #pragma unroll
        for (int ks = 0; ks < 4; ks++) {
            int kc = ks * 8 + t;
            int r = wid * 16 + g;
            float a0 = qs[r][kc],     a1 = qs[r + 8][kc];
            float a2 = qs[r][kc + 4], a3 = qs[r + 8][kc + 4];
            #pragma unroll
            for (int nt = 0; nt < 7; nt++) {
                int nr = nt * 8 + g;
                mma_tf32(sc[nt], a0, a1, a2, a3, ks_[nr][kc], ks_[nr][kc + 4]);
            }
        }

        // ---- scale + rel-bias + shift-mask -> ss ----
        #pragma unroll
        for (int nt = 0; nt < 7; nt++) {
            #pragma unroll
            for (int rh = 0; rh < 2; rh++) {
                int r = wid * 16 + g + rh * 8;
                #pragma unroll
                for (int j = 0; j < 2; j++) {
                    int cidx = nt * 8 + 2 * t + j;
                    float val;
                    if (r < NWIN && cidx < NWIN) {
                        int i1 = r / WS, j1 = r % WS, i2 = cidx / WS, j2 = cidx % WS;
                        int ridx = (i1 - i2 + WS - 1) * (2 * WS - 1) + (j1 - j2 + WS - 1);
                        val = sc[nt][rh * 2 + j] * scale
                            + relb[ridx * NHEADS + h] + mwin[r * NWIN + cidx];
                    } else {
                        val = -1e9f;
                    }
                    ss[r][cidx] = val;
                }
            }
        }
        __syncthreads();

        // ---- softmax (row per thread) ----
        if (tid < NWIN) {
            float mx = -1e30f;
            #pragma unroll 8
            for (int m = 0; m < 56; m++) mx = fmaxf(mx, ss[tid][m]);
            float sum = 0.f;
            float e[56];
            #pragma unroll 8
            for (int m = 0; m < 56; m++) { e[m] = __expf(ss[tid][m] - mx); sum += e[m]; }
            float inv = 1.0f / sum;
            #pragma unroll 8
            for (int m = 0; m < 56; m++) ss[tid][m] = to_tf32(e[m] * inv);
        }
        __syncthreads();

        // ---- O = P V ----
        float oc[4][4];
        #pragma unroll
        for (int nt = 0; nt < 4; nt++)
            #pragma unroll
            for (int l = 0; l < 4; l++) oc[nt][l] = 0.f;

        #pragma unroll
        for (int ks = 0; ks < 7; ks++) {
            int kc = ks * 8 + t;
            int r = wid * 16 + g;
            float a0 = ss[r][kc],     a1 = ss[r + 8][kc];
            float a2 = ss[r][kc + 4], a3 = ss[r + 8][kc + 4];
            #pragma unroll
            for (int nt = 0; nt < 4; nt++) {
                int nr = nt * 8 + g;
                mma_tf32(oc[nt], a0, a1, a2, a3, vt[nr][kc], vt[nr][kc + 4]);
            }
        }

        #pragma unroll
        for (int nt = 0; nt < 4; nt++) {
            #pragma unroll
            for (int rh = 0; rh < 2; rh++) {
                int r = wid * 16 + g + rh * 8;
                if (r < NWIN) {
                    #pragma unroll
                    for (int j = 0; j < 2; j++) {
                        int d = nt * 8 + 2 * t + j;
                        out[((size_t)win * NWIN + r) * CC + h * HD + d] = oc[nt][rh * 2 + j];
                    }
                }
            }
        }
        __syncthreads();
    }
}

// ---------------- launch ----------------
extern "C" void kernel_launch(void* const* d_in, const int* in_sizes, int n_in,
                              void* d_out, int out_size)
{
    const float* x      = (const float*)d_in[0];
    const float* mask   = (const float*)d_in[1];
    const float* n1g    = (const float*)d_in[2];
    const float* n1b    = (const float*)d_in[3];
    const float* qkv_w  = (const float*)d_in[4];
    const float* qkv_b  = (const float*)d_in[5];
    const float* relb   = (const float*)d_in[6];
    const float* proj_w = (const float*)d_in[7];
    const float* proj_b = (const float*)d_in[8];
    const float* n2g    = (const float*)d_in[9];
    const float* n2b    = (const float*)d_in[10];
    const float* fc1_w  = (const float*)d_in[11];
    const float* fc1_b  = (const float*)d_in[12];
    const float* fc2_w  = (const float*)d_in[13];
    const float* fc2_b  = (const float*)d_in[14];
    float* out = (float*)d_out;

    float *xw, *qkvb, *att, *x1, *y, *h1;
    cudaGetSymbolAddress((void**)&xw,   g_xw);
    cudaGetSymbolAddress((void**)&qkvb, g_qkv);
    cudaGetSymbolAddress((void**)&att,  g_att);
    cudaGetSymbolAddress((void**)&x1,   g_x1);
    cudaGetSymbolAddress((void**)&y,    g_y);
    cudaGetSymbolAddress((void**)&h1,   g_h1);

    const int LN_BLOCKS = M_TOK / 8;
    const int GM = M_TOK / 128;         // 1568

    ln_kernel<0><<<LN_BLOCKS, 256>>>(x, n1g, n1b, xw);
    gemm_tc<0><<<dim3(GM, 3), 384>>>(xw, qkv_w, qkv_b, qkvb, nullptr, CC, 3 * CC);
    attn_tc<<<BB * NW_IMG, 128>>>(qkvb, mask, relb, att);
    gemm_tc<2><<<dim3(GM, 1), 384>>>(att, proj_w, proj_b, x1, x, CC, CC);
    ln_kernel<1><<<LN_BLOCKS, 256>>>(x1, n2g, n2b, y);
    gemm_tc<1><<<dim3(GM, 4), 384>>>(y, fc1_w, fc1_b, h1, nullptr, CC, HID_D);
    gemm_tc<3><<<dim3(GM, 1), 384>>>(h1, fc2_w, fc2_b, out, x1, HID_D, CC);
}

// round 4
// speedup vs baseline: 2.3738x; 1.0581x over previous
#include <cuda_runtime.h>
#include <cuda_bf16.h>
#include <math.h>
#include <stdint.h>

// ---------------- problem constants ----------------
#define BB     16
#define HH     112
#define WWID   112
#define CC     96
#define NHEADS 3
#define HD     32
#define WS     7
#define NWIN   49
#define SHIFT  3
#define NW_IMG 256
#define M_TOK  200704
#define HID_D  384

typedef __nv_bfloat16 bf16;

// ---------------- scratch ----------------
__device__ bf16  g_xw [(size_t)M_TOK * CC];        // LN1 output (window layout)
__device__ bf16  g_qkv[(size_t)M_TOK * 3 * CC];    // qkv
__device__ bf16  g_att[(size_t)M_TOK * CC];        // attention out (window layout)
__device__ float g_x1 [(size_t)M_TOK * CC];        // residual 1 (fp32)
__device__ bf16  g_y  [(size_t)M_TOK * CC];        // LN2 output
__device__ bf16  g_h1 [(size_t)M_TOK * HID_D];     // fc1+gelu

// ---------------- mma helper ----------------
// mma.m16n8k16.row.col.f32.bf16.bf16.f32
//  A (16x16): a0=(g, 2t..2t+1) a1=(g+8, 2t..) a2=(g, 8+2t..) a3=(g+8, 8+2t..)
//  B (16x8):  b0=(k=2t..2t+1, n=g) b1=(k=8+2t.., n=g)
//  C: c0=(g,2t) c1=(g,2t+1) c2=(g+8,2t) c3=(g+8,2t+1)
__device__ __forceinline__ void mma_bf16(float* c, uint32_t a0, uint32_t a1,
                                         uint32_t a2, uint32_t a3,
                                         uint32_t b0, uint32_t b1) {
    asm volatile(
        "mma.sync.aligned.m16n8k16.row.col.f32.bf16.bf16.f32 "
        "{%0,%1,%2,%3}, {%4,%5,%6,%7}, {%8,%9}, {%0,%1,%2,%3};"
        : "+f"(c[0]), "+f"(c[1]), "+f"(c[2]), "+f"(c[3])
        : "r"(a0), "r"(a1), "r"(a2), "r"(a3), "r"(b0), "r"(b1));
}

__device__ __forceinline__ uint32_t pack_bf16x2(float lo, float hi) {
    uint32_t r;
    asm("cvt.rn.bf16x2.f32 %0, %1, %2;" : "=r"(r) : "f"(hi), "f"(lo));
    return r;
}

// ---------------- LayerNorm (warp per token), bf16 output ----------------
template<int MODE>
__global__ __launch_bounds__(256)
void ln_kernel(const float* __restrict__ x, const float* __restrict__ g,
               const float* __restrict__ beta, bf16* __restrict__ out)
{
    int t    = (blockIdx.x * blockDim.x + threadIdx.x) >> 5;
    int lane = threadIdx.x & 31;
    if (t >= M_TOK) return;

    const float* src;
    if (MODE == 0) {
        int win = t / NWIN, n = t % NWIN;
        int b  = win >> 8;
        int wi = win & 255;
        int wh = wi >> 4, ww = wi & 15;
        int i = n / WS, j = n % WS;
        int r = wh * WS + i + SHIFT; if (r >= HH)   r -= HH;
        int c = ww * WS + j + SHIFT; if (c >= WWID) c -= WWID;
        src = x + ((size_t)b * (HH * WWID) + r * WWID + c) * CC;
    } else {
        src = x + (size_t)t * CC;
    }

    float v0 = src[lane], v1 = src[lane + 32], v2 = src[lane + 64];
    float s = v0 + v1 + v2;
    #pragma unroll
    for (int o = 16; o; o >>= 1) s += __shfl_xor_sync(0xffffffffu, s, o);
    float mean = s * (1.0f / 96.0f);
    float d0 = v0 - mean, d1 = v1 - mean, d2 = v2 - mean;
    float q = d0 * d0 + d1 * d1 + d2 * d2;
    #pragma unroll
    for (int o = 16; o; o >>= 1) q += __shfl_xor_sync(0xffffffffu, q, o);
    float rstd = rsqrtf(q * (1.0f / 96.0f) + 1e-5f);

    bf16* dst = out + (size_t)t * CC;
    dst[lane]      = __float2bfloat16(d0 * rstd * g[lane]      + beta[lane]);
    dst[lane + 32] = __float2bfloat16(d1 * rstd * g[lane + 32] + beta[lane + 32]);
    dst[lane + 64] = __float2bfloat16(d2 * rstd * g[lane + 64] + beta[lane + 64]);
}

// ---------------- bf16 tensor-core GEMM: out = A(MxK,bf16) * W(NxK,f32)^T + bias
// BM=128, BN=96, BK=32, 384 threads (12 warps: 4m x 3n), warp tile 32x32
// EPI 0: bias -> bf16 | 1: bias+GELU -> bf16 | 2: bias+scatter+residual -> f32
// EPI 3: bias+residual -> f32
template<int EPI, typename OUTT>
__global__ __launch_bounds__(384)
void gemm_tc(const bf16* __restrict__ A, const float* __restrict__ W,
             const float* __restrict__ bias, OUTT* __restrict__ out,
             const float* __restrict__ res, int K, int N)
{
    __shared__ bf16 As[128][40];
    __shared__ bf16 Ws[96][40];

    int tid  = threadIdx.x;
    int wid  = tid >> 5, lane = tid & 31;
    int g    = lane >> 2, t = lane & 3;
    int wm   = wid & 3, wn = wid >> 2;
    int m0   = blockIdx.x * 128, n0 = blockIdx.y * 96;

    float c[2][4][4];
    #pragma unroll
    for (int i = 0; i < 2; i++)
        #pragma unroll
        for (int j = 0; j < 4; j++)
            #pragma unroll
            for (int l = 0; l < 4; l++) c[i][j][l] = 0.f;

    for (int kt = 0; kt < K; kt += 32) {
        // stage A: 128x32 bf16 = 512 uint4 chunks of 8 elems
        for (int idx = tid; idx < 512; idx += 384) {
            int row = idx >> 2, c8 = (idx & 3) << 3;
            uint4 v = *(const uint4*)(A + (size_t)(m0 + row) * K + kt + c8);
            *(uint4*)&As[row][c8] = v;
        }
        // stage W: 96x32 f32 -> bf16
        for (int idx = tid; idx < 768; idx += 384) {
            int row = idx >> 3, c4 = (idx & 7) << 2;
            float4 v = *(const float4*)(W + (size_t)(n0 + row) * K + kt + c4);
            uint2 p;
            p.x = pack_bf16x2(v.x, v.y);
            p.y = pack_bf16x2(v.z, v.w);
            *(uint2*)&Ws[row][c4] = p;
        }
        __syncthreads();

        #pragma unroll
        for (int ks = 0; ks < 2; ks++) {
            int kc = ks * 16 + 2 * t;
            uint32_t a[2][4];
            #pragma unroll
            for (int mt = 0; mt < 2; mt++) {
                int r = wm * 32 + mt * 16 + g;
                a[mt][0] = *(const uint32_t*)&As[r][kc];
                a[mt][1] = *(const uint32_t*)&As[r + 8][kc];
                a[mt][2] = *(const uint32_t*)&As[r][kc + 8];
                a[mt][3] = *(const uint32_t*)&As[r + 8][kc + 8];
            }
            #pragma unroll
            for (int nt = 0; nt < 4; nt++) {
                int nr = wn * 32 + nt * 8 + g;
                uint32_t b0 = *(const uint32_t*)&Ws[nr][kc];
                uint32_t b1 = *(const uint32_t*)&Ws[nr][kc + 8];
                #pragma unroll
                for (int mt = 0; mt < 2; mt++)
                    mma_bf16(c[mt][nt], a[mt][0], a[mt][1], a[mt][2], a[mt][3], b0, b1);
            }
        }
        __syncthreads();
    }

    #pragma unroll
    for (int mt = 0; mt < 2; mt++) {
        #pragma unroll
        for (int rh = 0; rh < 2; rh++) {
            int m = m0 + wm * 32 + mt * 16 + g + rh * 8;
            size_t rowbase;
            if (EPI == 2) {
                int win = m / NWIN, nn = m % NWIN;
                int b  = win >> 8;
                int wi = win & 255;
                int wh = wi >> 4, ww = wi & 15;
                int ii = nn / WS, jj = nn % WS;
                int r = wh * WS + ii + SHIFT; if (r >= HH)   r -= HH;
                int ccol = ww * WS + jj + SHIFT; if (ccol >= WWID) ccol -= WWID;
                rowbase = ((size_t)b * (HH * WWID) + r * WWID + ccol) * CC;
            } else {
                rowbase = (size_t)m * N;
            }
            #pragma unroll
            for (int nt = 0; nt < 4; nt++) {
                #pragma unroll
                for (int j = 0; j < 2; j++) {
                    int n = n0 + wn * 32 + nt * 8 + 2 * t + j;
                    float v = c[mt][nt][rh * 2 + j] + bias[n];
                    if (EPI == 0) {
                        out[rowbase + n] = (OUTT)__float2bfloat16(v);
                    } else if (EPI == 1) {
                        float gl = 0.5f * v * (1.0f + erff(v * 0.70710678118654752f));
                        out[rowbase + n] = (OUTT)__float2bfloat16(gl);
                    } else {
                        out[rowbase + n] = (OUTT)(res[rowbase + n] + v);
                    }
                }
            }
        }
    }
}

// ---------------- bf16 tensor-core window attention (block per window) -----
__global__ __launch_bounds__(128)
void attn_tc(const bf16* __restrict__ qkv, const float* __restrict__ mask,
             const float* __restrict__ relb, bf16* __restrict__ out)
{
    __shared__ bf16  qs [64][40];   // Q rows padded to 64
    __shared__ bf16  ks_[56][40];   // K rows padded to 56
    __shared__ bf16  vt [32][72];   // V^T: vt[d][key], keys padded to 64
    __shared__ bf16  pp [64][72];   // probs (bf16), keys padded to 64
    __shared__ float ss [64][57];   // raw scores

    int win  = blockIdx.x;
    int tid  = threadIdx.x;
    int wid  = tid >> 5, lane = tid & 31;
    int g    = lane >> 2, t = lane & 3;
    const float scale = 0.17677669529663689f;

    const float* mwin = mask + (size_t)(win & 255) * (NWIN * NWIN);
    const bf16*  base = qkv + (size_t)win * NWIN * (3 * CC);

    for (int h = 0; h < NHEADS; h++) {
        for (int p = tid; p < 64 * HD; p += 128) {
            int n = p >> 5, d = p & 31;
            qs[n][d] = (n < NWIN) ? base[(size_t)n * (3 * CC) + h * HD + d] : (bf16)0.f;
        }
        for (int p = tid; p < 64 * HD; p += 128) {
            int n = p >> 5, d = p & 31;
            bf16 kv = (n < NWIN) ? base[(size_t)n * (3 * CC) + CC + h * HD + d] : (bf16)0.f;
            bf16 vv = (n < NWIN) ? base[(size_t)n * (3 * CC) + 2 * CC + h * HD + d] : (bf16)0.f;
            if (n < 56) ks_[n][d] = kv;
            vt[d][n] = vv;
        }
        __syncthreads();

        // ---- S = Q K^T  (k=32 -> 2 k16 steps, 7 key n-tiles) ----
        float sc[7][4];
        #pragma unroll
        for (int nt = 0; nt < 7; nt++)
            #pragma unroll
            for (int l = 0; l < 4; l++) sc[nt][l] = 0.f;

        #pragma unroll
        for (int ks = 0; ks < 2; ks++) {
            int kc = ks * 16 + 2 * t;
            int r = wid * 16 + g;
            uint32_t a0 = *(const uint32_t*)&qs[r][kc];
            uint32_t a1 = *(const uint32_t*)&qs[r + 8][kc];
            uint32_t a2 = *(const uint32_t*)&qs[r][kc + 8];
            uint32_t a3 = *(const uint32_t*)&qs[r + 8][kc + 8];
            #pragma unroll
            for (int nt = 0; nt < 7; nt++) {
                int nr = nt * 8 + g;
                uint32_t b0 = *(const uint32_t*)&ks_[nr][kc];
                uint32_t b1 = *(const uint32_t*)&ks_[nr][kc + 8];
                mma_bf16(sc[nt], a0, a1, a2, a3, b0, b1);
            }
        }

        // ---- scale + rel-bias + shift-mask -> ss ----
        #pragma unroll
        for (int nt = 0; nt < 7; nt++) {
            #pragma unroll
            for (int rh = 0; rh < 2; rh++) {
                int r = wid * 16 + g + rh * 8;
                #pragma unroll
                for (int j = 0; j < 2; j++) {
                    int cidx = nt * 8 + 2 * t + j;
                    if (r < NWIN && cidx < 56) {
                        float val;
                        if (cidx < NWIN) {
                            int i1 = r / WS, j1 = r % WS, i2 = cidx / WS, j2 = cidx % WS;
                            int ridx = (i1 - i2 + WS - 1) * (2 * WS - 1) + (j1 - j2 + WS - 1);
                            val = sc[nt][rh * 2 + j] * scale
                                + relb[ridx * NHEADS + h] + mwin[r * NWIN + cidx];
                        } else {
                            val = -1e9f;
                        }
                        ss[r][cidx] = val;
                    }
                }
            }
        }
        __syncthreads();

        // ---- softmax (row per thread), write bf16 probs padded to 64 ----
        if (tid < NWIN) {
            float mx = -1e30f;
            #pragma unroll 8
            for (int m = 0; m < 56; m++) mx = fmaxf(mx, ss[tid][m]);
            float sum = 0.f;
            float e[56];
            #pragma unroll 8
            for (int m = 0; m < 56; m++) { e[m] = __expf(ss[tid][m] - mx); sum += e[m]; }
            float inv = 1.0f / sum;
            #pragma unroll 8
            for (int m = 0; m < 56; m++) pp[tid][m] = __float2bfloat16(e[m] * inv);
            #pragma unroll
            for (int m = 56; m < 64; m++) pp[tid][m] = (bf16)0.f;
        } else if (tid < 64) {
            #pragma unroll 8
            for (int m = 0; m < 64; m++) pp[tid][m] = (bf16)0.f;
        }
        __syncthreads();

        // ---- O = P V  (k=64 keys -> 4 k16 steps, 4 d n-tiles) ----
        float oc[4][4];
        #pragma unroll
        for (int nt = 0; nt < 4; nt++)
            #pragma unroll
            for (int l = 0; l < 4; l++) oc[nt][l] = 0.f;

        #pragma unroll
        for (int ks = 0; ks < 4; ks++) {
            int kc = ks * 16 + 2 * t;
            int r = wid * 16 + g;
            uint32_t a0 = *(const uint32_t*)&pp[r][kc];
            uint32_t a1 = *(const uint32_t*)&pp[r + 8][kc];
            uint32_t a2 = *(const uint32_t*)&pp[r][kc + 8];
            uint32_t a3 = *(const uint32_t*)&pp[r + 8][kc + 8];
            #pragma unroll
            for (int nt = 0; nt < 4; nt++) {
                int nr = nt * 8 + g;
                uint32_t b0 = *(const uint32_t*)&vt[nr][kc];
                uint32_t b1 = *(const uint32_t*)&vt[nr][kc + 8];
                mma_bf16(oc[nt], a0, a1, a2, a3, b0, b1);
            }
        }

        #pragma unroll
        for (int nt = 0; nt < 4; nt++) {
            #pragma unroll
            for (int rh = 0; rh < 2; rh++) {
                int r = wid * 16 + g + rh * 8;
                if (r < NWIN) {
                    #pragma unroll
                    for (int j = 0; j < 2; j++) {
                        int d = nt * 8 + 2 * t + j;
                        out[((size_t)win * NWIN + r) * CC + h * HD + d] =
                            __float2bfloat16(oc[nt][rh * 2 + j]);
                    }
                }
            }
        }
        __syncthreads();
    }
}

// ---------------- launch ----------------
extern "C" void kernel_launch(void* const* d_in, const int* in_sizes, int n_in,
                              void* d_out, int out_size)
{
    const float* x      = (const float*)d_in[0];
    const float* mask   = (const float*)d_in[1];
    const float* n1g    = (const float*)d_in[2];
    const float* n1b    = (const float*)d_in[3];
    const float* qkv_w  = (const float*)d_in[4];
    const float* qkv_b  = (const float*)d_in[5];
    const float* relb   = (const float*)d_in[6];
    const float* proj_w = (const float*)d_in[7];
    const float* proj_b = (const float*)d_in[8];
    const float* n2g    = (const float*)d_in[9];
    const float* n2b    = (const float*)d_in[10];
    const float* fc1_w  = (const float*)d_in[11];
    const float* fc1_b  = (const float*)d_in[12];
    const float* fc2_w  = (const float*)d_in[13];
    const float* fc2_b  = (const float*)d_in[14];
    float* out = (float*)d_out;

    bf16 *xw, *qkvb, *att, *y, *h1;
    float *x1;
    cudaGetSymbolAddress((void**)&xw,   g_xw);
    cudaGetSymbolAddress((void**)&qkvb, g_qkv);
    cudaGetSymbolAddress((void**)&att,  g_att);
    cudaGetSymbolAddress((void**)&x1,   g_x1);
    cudaGetSymbolAddress((void**)&y,    g_y);
    cudaGetSymbolAddress((void**)&h1,   g_h1);

    const int LN_BLOCKS = M_TOK / 8;
    const int GM = M_TOK / 128;         // 1568

    ln_kernel<0><<<LN_BLOCKS, 256>>>(x, n1g, n1b, xw);
    gemm_tc<0, bf16><<<dim3(GM, 3), 384>>>(xw, qkv_w, qkv_b, qkvb, nullptr, CC, 3 * CC);
    attn_tc<<<BB * NW_IMG, 128>>>(qkvb, mask, relb, att);
    gemm_tc<2, float><<<dim3(GM, 1), 384>>>(att, proj_w, proj_b, x1, x, CC, CC);
    ln_kernel<1><<<LN_BLOCKS, 256>>>(x1, n2g, n2b, y);
    gemm_tc<1, bf16><<<dim3(GM, 4), 384>>>(y, fc1_w, fc1_b, h1, nullptr, CC, HID_D);
    gemm_tc<3, float><<<dim3(GM, 1), 384>>>(h1, fc2_w, fc2_b, out, x1, HID_D, CC);
}

// round 5
// speedup vs baseline: 2.6776x; 1.1280x over previous
#include <cuda_runtime.h>
#include <cuda_bf16.h>
#include <math.h>
#include <stdint.h>

// ---------------- problem constants ----------------
#define BB     16
#define HH     112
#define WWID   112
#define CC     96
#define NHEADS 3
#define HD     32
#define WS     7
#define NWIN   49
#define SHIFT  3
#define NW_IMG 256
#define M_TOK  200704
#define HID_D  384

typedef __nv_bfloat16 bf16;

// weight buffer offsets (bf16, concatenated)
#define W_QKV  0
#define W_PROJ 27648
#define W_FC1  36864
#define W_FC2  73728
#define W_TOT  110592

// ---------------- scratch ----------------
__device__ bf16  g_xw [(size_t)M_TOK * CC];
__device__ bf16  g_qkv[(size_t)M_TOK * 3 * CC];
__device__ bf16  g_att[(size_t)M_TOK * CC];
__device__ float g_x1 [(size_t)M_TOK * CC];
__device__ bf16  g_y  [(size_t)M_TOK * CC];
__device__ bf16  g_h1 [(size_t)M_TOK * HID_D];
__device__ bf16  g_wb [W_TOT];

// ---------------- asm helpers ----------------
__device__ __forceinline__ void mma_bf16(float* c, uint32_t a0, uint32_t a1,
                                         uint32_t a2, uint32_t a3,
                                         uint32_t b0, uint32_t b1) {
    asm volatile(
        "mma.sync.aligned.m16n8k16.row.col.f32.bf16.bf16.f32 "
        "{%0,%1,%2,%3}, {%4,%5,%6,%7}, {%8,%9}, {%0,%1,%2,%3};"
        : "+f"(c[0]), "+f"(c[1]), "+f"(c[2]), "+f"(c[3])
        : "r"(a0), "r"(a1), "r"(a2), "r"(a3), "r"(b0), "r"(b1));
}

__device__ __forceinline__ void ldsm4(uint32_t& r0, uint32_t& r1,
                                      uint32_t& r2, uint32_t& r3, uint32_t addr) {
    asm volatile("ldmatrix.sync.aligned.m8n8.x4.shared.b16 {%0,%1,%2,%3}, [%4];"
                 : "=r"(r0), "=r"(r1), "=r"(r2), "=r"(r3) : "r"(addr));
}

__device__ __forceinline__ void cp16(uint32_t saddr, const void* g) {
    asm volatile("cp.async.ca.shared.global [%0], [%1], 16;" :: "r"(saddr), "l"(g));
}
__device__ __forceinline__ void cp_commit() { asm volatile("cp.async.commit_group;"); }
__device__ __forceinline__ void cp_wait1()  { asm volatile("cp.async.wait_group 1;"); }

// ---------------- weight fp32 -> bf16 convert ----------------
__global__ void convert_w(const float* __restrict__ qkv_w, const float* __restrict__ proj_w,
                          const float* __restrict__ fc1_w, const float* __restrict__ fc2_w,
                          bf16* __restrict__ wb)
{
    int i = blockIdx.x * 256 + threadIdx.x;
    if (i >= W_TOT) return;
    float v;
    if      (i < W_PROJ) v = qkv_w[i - W_QKV];
    else if (i < W_FC1)  v = proj_w[i - W_PROJ];
    else if (i < W_FC2)  v = fc1_w[i - W_FC1];
    else                 v = fc2_w[i - W_FC2];
    wb[i] = __float2bfloat16(v);
}

// ---------------- LayerNorm (warp per token), bf16 output ----------------
template<int MODE>
__global__ __launch_bounds__(256)
void ln_kernel(const float* __restrict__ x, const float* __restrict__ g,
               const float* __restrict__ beta, bf16* __restrict__ out)
{
    int t    = (blockIdx.x * blockDim.x + threadIdx.x) >> 5;
    int lane = threadIdx.x & 31;
    if (t >= M_TOK) return;

    const float* src;
    if (MODE == 0) {
        int win = t / NWIN, n = t % NWIN;
        int b  = win >> 8;
        int wi = win & 255;
        int wh = wi >> 4, ww = wi & 15;
        int i = n / WS, j = n % WS;
        int r = wh * WS + i + SHIFT; if (r >= HH)   r -= HH;
        int c = ww * WS + j + SHIFT; if (c >= WWID) c -= WWID;
        src = x + ((size_t)b * (HH * WWID) + r * WWID + c) * CC;
    } else {
        src = x + (size_t)t * CC;
    }

    float v0 = src[lane], v1 = src[lane + 32], v2 = src[lane + 64];
    float s = v0 + v1 + v2;
    #pragma unroll
    for (int o = 16; o; o >>= 1) s += __shfl_xor_sync(0xffffffffu, s, o);
    float mean = s * (1.0f / 96.0f);
    float d0 = v0 - mean, d1 = v1 - mean, d2 = v2 - mean;
    float q = d0 * d0 + d1 * d1 + d2 * d2;
    #pragma unroll
    for (int o = 16; o; o >>= 1) q += __shfl_xor_sync(0xffffffffu, q, o);
    float rstd = rsqrtf(q * (1.0f / 96.0f) + 1e-5f);

    bf16* dst = out + (size_t)t * CC;
    dst[lane]      = __float2bfloat16(d0 * rstd * g[lane]      + beta[lane]);
    dst[lane + 32] = __float2bfloat16(d1 * rstd * g[lane + 32] + beta[lane + 32]);
    dst[lane + 64] = __float2bfloat16(d2 * rstd * g[lane + 64] + beta[lane + 64]);
}

// ---------------- bf16 TC GEMM with cp.async pipeline + ldmatrix -----------
// out = A(MxK) * W(NxK)^T + bias. BM=128, BN=96, BK=32, 384 thr (12 warps 4m x 3n)
template<int EPI, typename OUTT>
__global__ __launch_bounds__(384)
void gemm_tc(const bf16* __restrict__ A, const bf16* __restrict__ W,
             const float* __restrict__ bias, OUTT* __restrict__ out,
             const float* __restrict__ res, int K, int N)
{
    __shared__ bf16 As[2][128][40];
    __shared__ bf16 Ws[2][96][40];

    int tid  = threadIdx.x;
    int wid  = tid >> 5, lane = tid & 31;
    int g    = lane >> 2, t = lane & 3;
    int wm   = wid & 3, wn = wid >> 2;
    int m0   = blockIdx.x * 128, n0 = blockIdx.y * 96;

    uint32_t as_base = (uint32_t)__cvta_generic_to_shared(&As[0][0][0]);
    uint32_t ws_base = (uint32_t)__cvta_generic_to_shared(&Ws[0][0][0]);

    // ldmatrix lane addressing offsets
    int lrow = lane & 7, lsel = lane >> 3;
    int ra = (lsel & 1) * 8 + lrow;    // row offset within 16-row block
    int caoff = (lsel >> 1) * 8;       // col offset (k half)

    float c[2][4][4];
    #pragma unroll
    for (int i = 0; i < 2; i++)
        #pragma unroll
        for (int j = 0; j < 4; j++)
            #pragma unroll
            for (int l = 0; l < 4; l++) c[i][j][l] = 0.f;

    int ktiles = K >> 5;

    // ---- staging lambda (cp.async 16B chunks) ----
    auto stage = [&](int buf, int kt) {
        // A: 128 rows x 32 cols = 512 chunks of 8 bf16
        {
            int idx = tid;
            int row = idx >> 2, c8 = (idx & 3) << 3;
            cp16(as_base + ((buf * 128 + row) * 40 + c8) * 2,
                 A + (size_t)(m0 + row) * K + kt * 32 + c8);
            if (tid < 128) {
                idx = tid + 384;
                row = idx >> 2; c8 = (idx & 3) << 3;
                cp16(as_base + ((buf * 128 + row) * 40 + c8) * 2,
                     A + (size_t)(m0 + row) * K + kt * 32 + c8);
            }
        }
        // W: 96 rows x 32 cols = 384 chunks
        {
            int row = tid >> 2, c8 = (tid & 3) << 3;
            cp16(ws_base + ((buf * 96 + row) * 40 + c8) * 2,
                 W + (size_t)(n0 + row) * K + kt * 32 + c8);
        }
    };

    stage(0, 0);
    cp_commit();

    for (int kt = 0; kt < ktiles; kt++) {
        int buf = kt & 1;
        if (kt + 1 < ktiles) stage((kt + 1) & 1, kt + 1);
        cp_commit();
        cp_wait1();
        __syncthreads();

        #pragma unroll
        for (int ks = 0; ks < 2; ks++) {
            int kc = ks * 16 + caoff;
            uint32_t a[2][4];
            #pragma unroll
            for (int mt = 0; mt < 2; mt++) {
                int row = wm * 32 + mt * 16 + ra;
                ldsm4(a[mt][0], a[mt][1], a[mt][2], a[mt][3],
                      as_base + ((buf * 128 + row) * 40 + kc) * 2);
            }
            uint32_t b[2][4];
            #pragma unroll
            for (int np = 0; np < 2; np++) {
                int row = wn * 32 + np * 16 + ra;
                ldsm4(b[np][0], b[np][1], b[np][2], b[np][3],
                      ws_base + ((buf * 96 + row) * 40 + kc) * 2);
            }
            // nt -> (b-pair, lo/hi): nt0:(b[0].r0,r2) nt1:(b[0].r1,r3) nt2:(b[1].r0,r2) nt3:(b[1].r1,r3)
            #pragma unroll
            for (int nt = 0; nt < 4; nt++) {
                uint32_t b0 = b[nt >> 1][nt & 1];
                uint32_t b1 = b[nt >> 1][(nt & 1) + 2];
                #pragma unroll
                for (int mt = 0; mt < 2; mt++)
                    mma_bf16(c[mt][nt], a[mt][0], a[mt][1], a[mt][2], a[mt][3], b0, b1);
            }
        }
        __syncthreads();
    }

    #pragma unroll
    for (int mt = 0; mt < 2; mt++) {
        #pragma unroll
        for (int rh = 0; rh < 2; rh++) {
            int m = m0 + wm * 32 + mt * 16 + g + rh * 8;
            size_t rowbase;
            if (EPI == 2) {
                int win = m / NWIN, nn = m % NWIN;
                int b  = win >> 8;
                int wi = win & 255;
                int wh = wi >> 4, ww = wi & 15;
                int ii = nn / WS, jj = nn % WS;
                int r = wh * WS + ii + SHIFT; if (r >= HH)   r -= HH;
                int ccol = ww * WS + jj + SHIFT; if (ccol >= WWID) ccol -= WWID;
                rowbase = ((size_t)b * (HH * WWID) + r * WWID + ccol) * CC;
            } else {
                rowbase = (size_t)m * N;
            }
            #pragma unroll
            for (int nt = 0; nt < 4; nt++) {
                #pragma unroll
                for (int j = 0; j < 2; j++) {
                    int n = n0 + wn * 32 + nt * 8 + 2 * t + j;
                    float v = c[mt][nt][rh * 2 + j] + bias[n];
                    if (EPI == 0) {
                        out[rowbase + n] = (OUTT)__float2bfloat16(v);
                    } else if (EPI == 1) {
                        float gl = 0.5f * v * (1.0f + erff(v * 0.70710678118654752f));
                        out[rowbase + n] = (OUTT)__float2bfloat16(gl);
                    } else {
                        out[rowbase + n] = (OUTT)(res[rowbase + n] + v);
                    }
                }
            }
        }
    }
}

// ---------------- bf16 tensor-core window attention (block per window) -----
__global__ __launch_bounds__(128)
void attn_tc(const bf16* __restrict__ qkv, const float* __restrict__ mask,
             const float* __restrict__ relb, bf16* __restrict__ out)
{
    __shared__ bf16  qs [64][40];
    __shared__ bf16  ks_[56][40];
    __shared__ bf16  vt [32][72];
    __shared__ bf16  pp [64][72];
    __shared__ float ss [64][57];

    int win  = blockIdx.x;
    int tid  = threadIdx.x;
    int wid  = tid >> 5, lane = tid & 31;
    int g    = lane >> 2, t = lane & 3;
    const float scale = 0.17677669529663689f;

    const float* mwin = mask + (size_t)(win & 255) * (NWIN * NWIN);
    const bf16*  base = qkv + (size_t)win * NWIN * (3 * CC);

    for (int h = 0; h < NHEADS; h++) {
        for (int p = tid; p < 64 * HD; p += 128) {
            int n = p >> 5, d = p & 31;
            qs[n][d] = (n < NWIN) ? base[(size_t)n * (3 * CC) + h * HD + d] : (bf16)0.f;
        }
        for (int p = tid; p < 64 * HD; p += 128) {
            int n = p >> 5, d = p & 31;
            bf16 kv = (n < NWIN) ? base[(size_t)n * (3 * CC) + CC + h * HD + d] : (bf16)0.f;
            bf16 vv = (n < NWIN) ? base[(size_t)n * (3 * CC) + 2 * CC + h * HD + d] : (bf16)0.f;
            if (n < 56) ks_[n][d] = kv;
            vt[d][n] = vv;
        }
        __syncthreads();

        float sc[7][4];
        #pragma unroll
        for (int nt = 0; nt < 7; nt++)
            #pragma unroll
            for (int l = 0; l < 4; l++) sc[nt][l] = 0.f;

        #pragma unroll
        for (int ks = 0; ks < 2; ks++) {
            int kc = ks * 16 + 2 * t;
            int r = wid * 16 + g;
            uint32_t a0 = *(const uint32_t*)&qs[r][kc];
            uint32_t a1 = *(const uint32_t*)&qs[r + 8][kc];
            uint32_t a2 = *(const uint32_t*)&qs[r][kc + 8];
            uint32_t a3 = *(const uint32_t*)&qs[r + 8][kc + 8];
            #pragma unroll
            for (int nt = 0; nt < 7; nt++) {
                int nr = nt * 8 + g;
                uint32_t b0 = *(const uint32_t*)&ks_[nr][kc];
                uint32_t b1 = *(const uint32_t*)&ks_[nr][kc + 8];
                mma_bf16(sc[nt], a0, a1, a2, a3, b0, b1);
            }
        }

        #pragma unroll
        for (int nt = 0; nt < 7; nt++) {
            #pragma unroll
            for (int rh = 0; rh < 2; rh++) {
                int r = wid * 16 + g + rh * 8;
                #pragma unroll
                for (int j = 0; j < 2; j++) {
                    int cidx = nt * 8 + 2 * t + j;
                    if (r < NWIN && cidx < 56) {
                        float val;
                        if (cidx < NWIN) {
                            int i1 = r / WS, j1 = r % WS, i2 = cidx / WS, j2 = cidx % WS;
                            int ridx = (i1 - i2 + WS - 1) * (2 * WS - 1) + (j1 - j2 + WS - 1);
                            val = sc[nt][rh * 2 + j] * scale
                                + relb[ridx * NHEADS + h] + mwin[r * NWIN + cidx];
                        } else {
                            val = -1e9f;
                        }
                        ss[r][cidx] = val;
                    }
                }
            }
        }
        __syncthreads();

        if (tid < NWIN) {
            float mx = -1e30f;
            #pragma unroll 8
            for (int m = 0; m < 56; m++) mx = fmaxf(mx, ss[tid][m]);
            float sum = 0.f;
            float e[56];
            #pragma unroll 8
            for (int m = 0; m < 56; m++) { e[m] = __expf(ss[tid][m] - mx); sum += e[m]; }
            float inv = 1.0f / sum;
            #pragma unroll 8
            for (int m = 0; m < 56; m++) pp[tid][m] = __float2bfloat16(e[m] * inv);
            #pragma unroll
            for (int m = 56; m < 64; m++) pp[tid][m] = (bf16)0.f;
        } else if (tid < 64) {
            #pragma unroll 8
            for (int m = 0; m < 64; m++) pp[tid][m] = (bf16)0.f;
        }
        __syncthreads();

        float oc[4][4];
        #pragma unroll
        for (int nt = 0; nt < 4; nt++)
            #pragma unroll
            for (int l = 0; l < 4; l++) oc[nt][l] = 0.f;

        #pragma unroll
        for (int ks = 0; ks < 4; ks++) {
            int kc = ks * 16 + 2 * t;
            int r = wid * 16 + g;
            uint32_t a0 = *(const uint32_t*)&pp[r][kc];
            uint32_t a1 = *(const uint32_t*)&pp[r + 8][kc];
            uint32_t a2 = *(const uint32_t*)&pp[r][kc + 8];
            uint32_t a3 = *(const uint32_t*)&pp[r + 8][kc + 8];
            #pragma unroll
            for (int nt = 0; nt < 4; nt++) {
                int nr = nt * 8 + g;
                uint32_t b0 = *(const uint32_t*)&vt[nr][kc];
                uint32_t b1 = *(const uint32_t*)&vt[nr][kc + 8];
                mma_bf16(oc[nt], a0, a1, a2, a3, b0, b1);
            }
        }

        #pragma unroll
        for (int nt = 0; nt < 4; nt++) {
            #pragma unroll
            for (int rh = 0; rh < 2; rh++) {
                int r = wid * 16 + g + rh * 8;
                if (r < NWIN) {
                    #pragma unroll
                    for (int j = 0; j < 2; j++) {
                        int d = nt * 8 + 2 * t + j;
                        out[((size_t)win * NWIN + r) * CC + h * HD + d] =
                            __float2bfloat16(oc[nt][rh * 2 + j]);
                    }
                }
            }
        }
        __syncthreads();
    }
}

// ---------------- launch ----------------
extern "C" void kernel_launch(void* const* d_in, const int* in_sizes, int n_in,
                              void* d_out, int out_size)
{
    const float* x      = (const float*)d_in[0];
    const float* mask   = (const float*)d_in[1];
    const float* n1g    = (const float*)d_in[2];
    const float* n1b    = (const float*)d_in[3];
    const float* qkv_w  = (const float*)d_in[4];
    const float* qkv_b  = (const float*)d_in[5];
    const float* relb   = (const float*)d_in[6];
    const float* proj_w = (const float*)d_in[7];
    const float* proj_b = (const float*)d_in[8];
    const float* n2g    = (const float*)d_in[9];
    const float* n2b    = (const float*)d_in[10];
    const float* fc1_w  = (const float*)d_in[11];
    const float* fc1_b  = (const float*)d_in[12];
    const float* fc2_w  = (const float*)d_in[13];
    const float* fc2_b  = (const float*)d_in[14];
    float* out = (float*)d_out;

    bf16 *xw, *qkvb, *att, *y, *h1, *wb;
    float *x1;
    cudaGetSymbolAddress((void**)&xw,   g_xw);
    cudaGetSymbolAddress((void**)&qkvb, g_qkv);
    cudaGetSymbolAddress((void**)&att,  g_att);
    cudaGetSymbolAddress((void**)&x1,   g_x1);
    cudaGetSymbolAddress((void**)&y,    g_y);
    cudaGetSymbolAddress((void**)&h1,   g_h1);
    cudaGetSymbolAddress((void**)&wb,   g_wb);

    const int LN_BLOCKS = M_TOK / 8;
    const int GM = M_TOK / 128;         // 1568

    convert_w<<<(W_TOT + 255) / 256, 256>>>(qkv_w, proj_w, fc1_w, fc2_w, wb);
    ln_kernel<0><<<LN_BLOCKS, 256>>>(x, n1g, n1b, xw);
    gemm_tc<0, bf16><<<dim3(GM, 3), 384>>>(xw, wb + W_QKV, qkv_b, qkvb, nullptr, CC, 3 * CC);
    attn_tc<<<BB * NW_IMG, 128>>>(qkvb, mask, relb, att);
    gemm_tc<2, float><<<dim3(GM, 1), 384>>>(att, wb + W_PROJ, proj_b, x1, x, CC, CC);
    ln_kernel<1><<<LN_BLOCKS, 256>>>(x1, n2g, n2b, y);
    gemm_tc<1, bf16><<<dim3(GM, 4), 384>>>(y, wb + W_FC1, fc1_b, h1, nullptr, CC, HID_D);
    gemm_tc<3, float><<<dim3(GM, 1), 384>>>(h1, wb + W_FC2, fc2_b, out, x1, HID_D, CC);
}

// round 6
// speedup vs baseline: 3.1198x; 1.1652x over previous
#include <cuda_runtime.h>
#include <cuda_bf16.h>
#include <math.h>
#include <stdint.h>

// ---------------- problem constants ----------------
#define BB     16
#define HH     112
#define WWID   112
#define CC     96
#define NHEADS 3
#define HD     32
#define WS     7
#define NWIN   49
#define SHIFT  3
#define NW_IMG 256
#define M_TOK  200704
#define HID_D  384

typedef __nv_bfloat16 bf16;

// weight buffer offsets (bf16, concatenated)
#define W_QKV  0
#define W_PROJ 27648
#define W_FC1  36864
#define W_FC2  73728
#define W_TOT  110592

#define BM_ELEMS (256 * 3 * 49 * 56)

// ---------------- scratch ----------------
__device__ bf16  g_xw [(size_t)M_TOK * CC];
__device__ bf16  g_qkv[(size_t)M_TOK * 3 * CC];
__device__ bf16  g_att[(size_t)M_TOK * CC];
__device__ float g_x1 [(size_t)M_TOK * CC];
__device__ bf16  g_y  [(size_t)M_TOK * CC];
__device__ bf16  g_h1 [(size_t)M_TOK * HID_D];
__device__ bf16  g_wb [W_TOT];
__device__ float g_bm [BM_ELEMS];      // combined rel-bias + shift-mask, padded cols

// ---------------- asm helpers ----------------
__device__ __forceinline__ void mma_bf16(float* c, uint32_t a0, uint32_t a1,
                                         uint32_t a2, uint32_t a3,
                                         uint32_t b0, uint32_t b1) {
    asm volatile(
        "mma.sync.aligned.m16n8k16.row.col.f32.bf16.bf16.f32 "
        "{%0,%1,%2,%3}, {%4,%5,%6,%7}, {%8,%9}, {%0,%1,%2,%3};"
        : "+f"(c[0]), "+f"(c[1]), "+f"(c[2]), "+f"(c[3])
        : "r"(a0), "r"(a1), "r"(a2), "r"(a3), "r"(b0), "r"(b1));
}

__device__ __forceinline__ void ldsm4(uint32_t& r0, uint32_t& r1,
                                      uint32_t& r2, uint32_t& r3, uint32_t addr) {
    asm volatile("ldmatrix.sync.aligned.m8n8.x4.shared.b16 {%0,%1,%2,%3}, [%4];"
                 : "=r"(r0), "=r"(r1), "=r"(r2), "=r"(r3) : "r"(addr));
}

__device__ __forceinline__ void cp16(uint32_t saddr, const void* g) {
    asm volatile("cp.async.ca.shared.global [%0], [%1], 16;" :: "r"(saddr), "l"(g));
}
__device__ __forceinline__ void cp_commit() { asm volatile("cp.async.commit_group;"); }
__device__ __forceinline__ void cp_wait1()  { asm volatile("cp.async.wait_group 1;"); }

__device__ __forceinline__ uint32_t pack_bf16x2(float lo, float hi) {
    uint32_t r;
    asm("cvt.rn.bf16x2.f32 %0, %1, %2;" : "=r"(r) : "f"(hi), "f"(lo));
    return r;
}

// ---------------- setup: weights fp32->bf16 ----------------
__global__ void convert_w(const float* __restrict__ qkv_w, const float* __restrict__ proj_w,
                          const float* __restrict__ fc1_w, const float* __restrict__ fc2_w,
                          bf16* __restrict__ wb)
{
    int i = blockIdx.x * 256 + threadIdx.x;
    if (i >= W_TOT) return;
    float v;
    if      (i < W_PROJ) v = qkv_w[i - W_QKV];
    else if (i < W_FC1)  v = proj_w[i - W_PROJ];
    else if (i < W_FC2)  v = fc1_w[i - W_FC1];
    else                 v = fc2_w[i - W_FC2];
    wb[i] = __float2bfloat16(v);
}

// ---------------- setup: combined bias+mask table --------------------------
// bm[wi][h][r][c56]: c<49 -> relb[ridx*3+h] + mask[wi][r][c]; c>=49 -> -1e9
__global__ void build_bm(const float* __restrict__ relb, const float* __restrict__ mask,
                         float* __restrict__ bm)
{
    int idx = blockIdx.x * 256 + threadIdx.x;
    if (idx >= BM_ELEMS) return;
    int c   = idx % 56;
    int tmp = idx / 56;
    int r   = tmp % 49;  tmp /= 49;
    int h   = tmp % 3;
    int wi  = tmp / 3;
    float v;
    if (c < 49) {
        int i1 = r / WS, j1 = r % WS, i2 = c / WS, j2 = c % WS;
        int ridx = (i1 - i2 + WS - 1) * (2 * WS - 1) + (j1 - j2 + WS - 1);
        v = relb[ridx * NHEADS + h] + mask[(size_t)wi * (NWIN * NWIN) + r * NWIN + c];
    } else {
        v = -1e9f;
    }
    bm[idx] = v;
}

// ---------------- LayerNorm (warp per token), bf16 output ----------------
template<int MODE>
__global__ __launch_bounds__(256)
void ln_kernel(const float* __restrict__ x, const float* __restrict__ g,
               const float* __restrict__ beta, bf16* __restrict__ out)
{
    int t    = (blockIdx.x * blockDim.x + threadIdx.x) >> 5;
    int lane = threadIdx.x & 31;
    if (t >= M_TOK) return;

    const float* src;
    if (MODE == 0) {
        int win = t / NWIN, n = t % NWIN;
        int b  = win >> 8;
        int wi = win & 255;
        int wh = wi >> 4, ww = wi & 15;
        int i = n / WS, j = n % WS;
        int r = wh * WS + i + SHIFT; if (r >= HH)   r -= HH;
        int c = ww * WS + j + SHIFT; if (c >= WWID) c -= WWID;
        src = x + ((size_t)b * (HH * WWID) + r * WWID + c) * CC;
    } else {
        src = x + (size_t)t * CC;
    }

    float v0 = src[lane], v1 = src[lane + 32], v2 = src[lane + 64];
    float s = v0 + v1 + v2;
    #pragma unroll
    for (int o = 16; o; o >>= 1) s += __shfl_xor_sync(0xffffffffu, s, o);
    float mean = s * (1.0f / 96.0f);
    float d0 = v0 - mean, d1 = v1 - mean, d2 = v2 - mean;
    float q = d0 * d0 + d1 * d1 + d2 * d2;
    #pragma unroll
    for (int o = 16; o; o >>= 1) q += __shfl_xor_sync(0xffffffffu, q, o);
    float rstd = rsqrtf(q * (1.0f / 96.0f) + 1e-5f);

    bf16* dst = out + (size_t)t * CC;
    dst[lane]      = __float2bfloat16(d0 * rstd * g[lane]      + beta[lane]);
    dst[lane + 32] = __float2bfloat16(d1 * rstd * g[lane + 32] + beta[lane + 32]);
    dst[lane + 64] = __float2bfloat16(d2 * rstd * g[lane + 64] + beta[lane + 64]);
}

// ---------------- bf16 TC GEMM with cp.async pipeline + ldmatrix -----------
template<int EPI, typename OUTT>
__global__ __launch_bounds__(384)
void gemm_tc(const bf16* __restrict__ A, const bf16* __restrict__ W,
             const float* __restrict__ bias, OUTT* __restrict__ out,
             const float* __restrict__ res, int K, int N)
{
    __shared__ bf16 As[2][128][40];
    __shared__ bf16 Ws[2][96][40];

    int tid  = threadIdx.x;
    int wid  = tid >> 5, lane = tid & 31;
    int g    = lane >> 2, t = lane & 3;
    int wm   = wid & 3, wn = wid >> 2;
    int m0   = blockIdx.x * 128, n0 = blockIdx.y * 96;

    uint32_t as_base = (uint32_t)__cvta_generic_to_shared(&As[0][0][0]);
    uint32_t ws_base = (uint32_t)__cvta_generic_to_shared(&Ws[0][0][0]);

    int lrow = lane & 7, lsel = lane >> 3;
    int ra = (lsel & 1) * 8 + lrow;
    int caoff = (lsel >> 1) * 8;

    float c[2][4][4];
    #pragma unroll
    for (int i = 0; i < 2; i++)
        #pragma unroll
        for (int j = 0; j < 4; j++)
            #pragma unroll
            for (int l = 0; l < 4; l++) c[i][j][l] = 0.f;

    int ktiles = K >> 5;

    auto stage = [&](int buf, int kt) {
        {
            int idx = tid;
            int row = idx >> 2, c8 = (idx & 3) << 3;
            cp16(as_base + ((buf * 128 + row) * 40 + c8) * 2,
                 A + (size_t)(m0 + row) * K + kt * 32 + c8);
            if (tid < 128) {
                idx = tid + 384;
                row = idx >> 2; c8 = (idx & 3) << 3;
                cp16(as_base + ((buf * 128 + row) * 40 + c8) * 2,
                     A + (size_t)(m0 + row) * K + kt * 32 + c8);
            }
        }
        {
            int row = tid >> 2, c8 = (tid & 3) << 3;
            cp16(ws_base + ((buf * 96 + row) * 40 + c8) * 2,
                 W + (size_t)(n0 + row) * K + kt * 32 + c8);
        }
    };

    stage(0, 0);
    cp_commit();

    for (int kt = 0; kt < ktiles; kt++) {
        int buf = kt & 1;
        if (kt + 1 < ktiles) stage((kt + 1) & 1, kt + 1);
        cp_commit();
        cp_wait1();
        __syncthreads();

        #pragma unroll
        for (int ks = 0; ks < 2; ks++) {
            int kc = ks * 16 + caoff;
            uint32_t a[2][4];
            #pragma unroll
            for (int mt = 0; mt < 2; mt++) {
                int row = wm * 32 + mt * 16 + ra;
                ldsm4(a[mt][0], a[mt][1], a[mt][2], a[mt][3],
                      as_base + ((buf * 128 + row) * 40 + kc) * 2);
            }
            uint32_t b[2][4];
            #pragma unroll
            for (int np = 0; np < 2; np++) {
                int row = wn * 32 + np * 16 + ra;
                ldsm4(b[np][0], b[np][1], b[np][2], b[np][3],
                      ws_base + ((buf * 96 + row) * 40 + kc) * 2);
            }
            #pragma unroll
            for (int nt = 0; nt < 4; nt++) {
                uint32_t b0 = b[nt >> 1][nt & 1];
                uint32_t b1 = b[nt >> 1][(nt & 1) + 2];
                #pragma unroll
                for (int mt = 0; mt < 2; mt++)
                    mma_bf16(c[mt][nt], a[mt][0], a[mt][1], a[mt][2], a[mt][3], b0, b1);
            }
        }
        __syncthreads();
    }

    #pragma unroll
    for (int mt = 0; mt < 2; mt++) {
        #pragma unroll
        for (int rh = 0; rh < 2; rh++) {
            int m = m0 + wm * 32 + mt * 16 + g + rh * 8;
            size_t rowbase;
            if (EPI == 2) {
                int win = m / NWIN, nn = m % NWIN;
                int b  = win >> 8;
                int wi = win & 255;
                int wh = wi >> 4, ww = wi & 15;
                int ii = nn / WS, jj = nn % WS;
                int r = wh * WS + ii + SHIFT; if (r >= HH)   r -= HH;
                int ccol = ww * WS + jj + SHIFT; if (ccol >= WWID) ccol -= WWID;
                rowbase = ((size_t)b * (HH * WWID) + r * WWID + ccol) * CC;
            } else {
                rowbase = (size_t)m * N;
            }
            #pragma unroll
            for (int nt = 0; nt < 4; nt++) {
                #pragma unroll
                for (int j = 0; j < 2; j++) {
                    int n = n0 + wn * 32 + nt * 8 + 2 * t + j;
                    float v = c[mt][nt][rh * 2 + j] + bias[n];
                    if (EPI == 0) {
                        out[rowbase + n] = (OUTT)__float2bfloat16(v);
                    } else if (EPI == 1) {
                        float gl = 0.5f * v * (1.0f + erff(v * 0.70710678118654752f));
                        out[rowbase + n] = (OUTT)__float2bfloat16(gl);
                    } else {
                        out[rowbase + n] = (OUTT)(res[rowbase + n] + v);
                    }
                }
            }
        }
    }
}

// ---------------- attention: register softmax, P-in-register PV ------------
__global__ __launch_bounds__(128)
void attn_tc(const bf16* __restrict__ qkv, const float* __restrict__ bm,
             bf16* __restrict__ out)
{
    __shared__ bf16 qs [64][40];   // Q rows padded to 64
    __shared__ bf16 ks_[56][40];   // K rows padded to 56
    __shared__ bf16 vt [32][72];   // V^T: vt[d][key], keys zero-padded to 64

    int win  = blockIdx.x;
    int tid  = threadIdx.x;
    int wid  = tid >> 5, lane = tid & 31;
    int g    = lane >> 2, t = lane & 3;
    const float scale = 0.17677669529663689f;

    const bf16* base = qkv + (size_t)win * NWIN * (3 * CC);
    int r0 = wid * 16 + g, r1 = r0 + 8;
    bool v0ok = r0 < NWIN, v1ok = r1 < NWIN;

    for (int h = 0; h < NHEADS; h++) {
        // ---- stage Q / K / V^T ----
        for (int p = tid; p < 64 * HD; p += 128) {
            int n = p >> 5, d = p & 31;
            qs[n][d] = (n < NWIN) ? base[(size_t)n * (3 * CC) + h * HD + d] : (bf16)0.f;
        }
        for (int p = tid; p < 64 * HD; p += 128) {
            int n = p >> 5, d = p & 31;
            bf16 kv = (n < NWIN) ? base[(size_t)n * (3 * CC) + CC + h * HD + d] : (bf16)0.f;
            bf16 vv = (n < NWIN) ? base[(size_t)n * (3 * CC) + 2 * CC + h * HD + d] : (bf16)0.f;
            if (n < 56) ks_[n][d] = kv;
            vt[d][n] = vv;
        }
        __syncthreads();

        // ---- S = Q K^T ----
        float sc[7][4];
        #pragma unroll
        for (int nt = 0; nt < 7; nt++)
            #pragma unroll
            for (int l = 0; l < 4; l++) sc[nt][l] = 0.f;

        #pragma unroll
        for (int ks = 0; ks < 2; ks++) {
            int kc = ks * 16 + 2 * t;
            uint32_t a0 = *(const uint32_t*)&qs[r0][kc];
            uint32_t a1 = *(const uint32_t*)&qs[r1][kc];
            uint32_t a2 = *(const uint32_t*)&qs[r0][kc + 8];
            uint32_t a3 = *(const uint32_t*)&qs[r1][kc + 8];
            #pragma unroll
            for (int nt = 0; nt < 7; nt++) {
                int nr = nt * 8 + g;
                uint32_t b0 = *(const uint32_t*)&ks_[nr][kc];
                uint32_t b1 = *(const uint32_t*)&ks_[nr][kc + 8];
                mma_bf16(sc[nt], a0, a1, a2, a3, b0, b1);
            }
        }

        // ---- scale + combined bias/mask (L2-resident table) ----
        const float* bmh = bm + ((size_t)((win & 255) * 3 + h)) * (49 * 56);
        #pragma unroll
        for (int nt = 0; nt < 7; nt++) {
            int cbase = nt * 8 + 2 * t;
            #pragma unroll
            for (int j = 0; j < 2; j++) {
                sc[nt][j]     = v0ok ? sc[nt][j]     * scale + bmh[r0 * 56 + cbase + j] : 0.f;
                sc[nt][2 + j] = v1ok ? sc[nt][2 + j] * scale + bmh[r1 * 56 + cbase + j] : 0.f;
            }
        }

        // ---- softmax in registers (quad reduction across t) ----
        float mx0 = -1e30f, mx1 = -1e30f;
        #pragma unroll
        for (int nt = 0; nt < 7; nt++) {
            mx0 = fmaxf(mx0, fmaxf(sc[nt][0], sc[nt][1]));
            mx1 = fmaxf(mx1, fmaxf(sc[nt][2], sc[nt][3]));
        }
        #pragma unroll
        for (int o = 1; o <= 2; o <<= 1) {
            mx0 = fmaxf(mx0, __shfl_xor_sync(0xffffffffu, mx0, o));
            mx1 = fmaxf(mx1, __shfl_xor_sync(0xffffffffu, mx1, o));
        }
        float sum0 = 0.f, sum1 = 0.f;
        #pragma unroll
        for (int nt = 0; nt < 7; nt++) {
            sc[nt][0] = __expf(sc[nt][0] - mx0); sum0 += sc[nt][0];
            sc[nt][1] = __expf(sc[nt][1] - mx0); sum0 += sc[nt][1];
            sc[nt][2] = __expf(sc[nt][2] - mx1); sum1 += sc[nt][2];
            sc[nt][3] = __expf(sc[nt][3] - mx1); sum1 += sc[nt][3];
        }
        #pragma unroll
        for (int o = 1; o <= 2; o <<= 1) {
            sum0 += __shfl_xor_sync(0xffffffffu, sum0, o);
            sum1 += __shfl_xor_sync(0xffffffffu, sum1, o);
        }
        float inv0 = 1.0f / sum0, inv1 = 1.0f / sum1;
        #pragma unroll
        for (int nt = 0; nt < 7; nt++) {
            sc[nt][0] *= inv0; sc[nt][1] *= inv0;
            sc[nt][2] *= inv1; sc[nt][3] *= inv1;
        }

        // ---- O = P V : P fragments come straight from sc registers ----
        float oc[4][4];
        #pragma unroll
        for (int nt = 0; nt < 4; nt++)
            #pragma unroll
            for (int l = 0; l < 4; l++) oc[nt][l] = 0.f;

        #pragma unroll
        for (int ks = 0; ks < 4; ks++) {
            uint32_t a0 = pack_bf16x2(sc[2 * ks][0], sc[2 * ks][1]);
            uint32_t a1 = pack_bf16x2(sc[2 * ks][2], sc[2 * ks][3]);
            uint32_t a2 = 0, a3 = 0;
            if (ks < 3) {
                a2 = pack_bf16x2(sc[2 * ks + 1][0], sc[2 * ks + 1][1]);
                a3 = pack_bf16x2(sc[2 * ks + 1][2], sc[2 * ks + 1][3]);
            }
            int kc = ks * 16 + 2 * t;
            #pragma unroll
            for (int nt = 0; nt < 4; nt++) {
                int nr = nt * 8 + g;
                uint32_t b0 = *(const uint32_t*)&vt[nr][kc];
                uint32_t b1 = *(const uint32_t*)&vt[nr][kc + 8];
                mma_bf16(oc[nt], a0, a1, a2, a3, b0, b1);
            }
        }

        #pragma unroll
        for (int nt = 0; nt < 4; nt++) {
            #pragma unroll
            for (int j = 0; j < 2; j++) {
                int d = nt * 8 + 2 * t + j;
                if (v0ok)
                    out[((size_t)win * NWIN + r0) * CC + h * HD + d] =
                        __float2bfloat16(oc[nt][j]);
                if (v1ok)
                    out[((size_t)win * NWIN + r1) * CC + h * HD + d] =
                        __float2bfloat16(oc[nt][2 + j]);
            }
        }
        __syncthreads();
    }
}

// ---------------- launch ----------------
extern "C" void kernel_launch(void* const* d_in, const int* in_sizes, int n_in,
                              void* d_out, int out_size)
{
    const float* x      = (const float*)d_in[0];
    const float* mask   = (const float*)d_in[1];
    const float* n1g    = (const float*)d_in[2];
    const float* n1b    = (const float*)d_in[3];
    const float* qkv_w  = (const float*)d_in[4];
    const float* qkv_b  = (const float*)d_in[5];
    const float* relb   = (const float*)d_in[6];
    const float* proj_w = (const float*)d_in[7];
    const float* proj_b = (const float*)d_in[8];
    const float* n2g    = (const float*)d_in[9];
    const float* n2b    = (const float*)d_in[10];
    const float* fc1_w  = (const float*)d_in[11];
    const float* fc1_b  = (const float*)d_in[12];
    const float* fc2_w  = (const float*)d_in[13];
    const float* fc2_b  = (const float*)d_in[14];
    float* out = (float*)d_out;

    bf16 *xw, *qkvb, *att, *y, *h1, *wb;
    float *x1, *bm;
    cudaGetSymbolAddress((void**)&xw,   g_xw);
    cudaGetSymbolAddress((void**)&qkvb, g_qkv);
    cudaGetSymbolAddress((void**)&att,  g_att);
    cudaGetSymbolAddress((void**)&x1,   g_x1);
    cudaGetSymbolAddress((void**)&y,    g_y);
    cudaGetSymbolAddress((void**)&h1,   g_h1);
    cudaGetSymbolAddress((void**)&wb,   g_wb);
    cudaGetSymbolAddress((void**)&bm,   g_bm);

    const int LN_BLOCKS = M_TOK / 8;
    const int GM = M_TOK / 128;         // 1568

    convert_w<<<(W_TOT + 255) / 256, 256>>>(qkv_w, proj_w, fc1_w, fc2_w, wb);
    build_bm<<<(BM_ELEMS + 255) / 256, 256>>>(relb, mask, bm);
    ln_kernel<0><<<LN_BLOCKS, 256>>>(x, n1g, n1b, xw);
    gemm_tc<0, bf16><<<dim3(GM, 3), 384>>>(xw, wb + W_QKV, qkv_b, qkvb, nullptr, CC, 3 * CC);
    attn_tc<<<BB * NW_IMG, 128>>>(qkvb, bm, att);
    gemm_tc<2, float><<<dim3(GM, 1), 384>>>(att, wb + W_PROJ, proj_b, x1, x, CC, CC);
    ln_kernel<1><<<LN_BLOCKS, 256>>>(x1, n2g, n2b, y);
    gemm_tc<1, bf16><<<dim3(GM, 4), 384>>>(y, wb + W_FC1, fc1_b, h1, nullptr, CC, HID_D);
    gemm_tc<3, float><<<dim3(GM, 1), 384>>>(h1, wb + W_FC2, fc2_b, out, x1, HID_D, CC);
}

// round 8
// speedup vs baseline: 3.3580x; 1.0763x over previous
#include <cuda_runtime.h>
#include <cuda_bf16.h>
#include <math.h>
#include <stdint.h>

// ---------------- problem constants ----------------
#define BB     16
#define HH     112
#define WWID   112
#define CC     96
#define NHEADS 3
#define HD     32
#define WS     7
#define NWIN   49
#define SHIFT  3
#define NW_IMG 256
#define M_TOK  200704
#define HID_D  384

typedef __nv_bfloat16 bf16;

// weight buffer offsets (bf16, concatenated)
#define W_QKV  0
#define W_PROJ 27648
#define W_FC1  36864
#define W_FC2  73728
#define W_TOT  110592

#define BM_ELEMS (256 * 3 * 49 * 56)

// smem row stride (bf16 elems): 96+8 -> conflict-free ldmatrix (13*16B rows)
#define SSTR 104

// ---------------- scratch ----------------
__device__ bf16  g_xw [(size_t)M_TOK * CC];
__device__ bf16  g_qkv[(size_t)M_TOK * 3 * CC];
__device__ bf16  g_att[(size_t)M_TOK * CC];
__device__ float g_x1 [(size_t)M_TOK * CC];
__device__ bf16  g_y  [(size_t)M_TOK * CC];
__device__ bf16  g_h1 [(size_t)M_TOK * HID_D];
__device__ bf16  g_wb [W_TOT];
__device__ float g_bm [BM_ELEMS];

// ---------------- asm helpers ----------------
__device__ __forceinline__ void mma_bf16(float* c, uint32_t a0, uint32_t a1,
                                         uint32_t a2, uint32_t a3,
                                         uint32_t b0, uint32_t b1) {
    asm volatile(
        "mma.sync.aligned.m16n8k16.row.col.f32.bf16.bf16.f32 "
        "{%0,%1,%2,%3}, {%4,%5,%6,%7}, {%8,%9}, {%0,%1,%2,%3};"
        : "+f"(c[0]), "+f"(c[1]), "+f"(c[2]), "+f"(c[3])
        : "r"(a0), "r"(a1), "r"(a2), "r"(a3), "r"(b0), "r"(b1));
}

__device__ __forceinline__ void ldsm4(uint32_t& r0, uint32_t& r1,
                                      uint32_t& r2, uint32_t& r3, uint32_t addr) {
    asm volatile("ldmatrix.sync.aligned.m8n8.x4.shared.b16 {%0,%1,%2,%3}, [%4];"
                 : "=r"(r0), "=r"(r1), "=r"(r2), "=r"(r3) : "r"(addr));
}

__device__ __forceinline__ void cp16(uint32_t saddr, const void* g) {
    asm volatile("cp.async.ca.shared.global [%0], [%1], 16;" :: "r"(saddr), "l"(g));
}
__device__ __forceinline__ void cp_commit() { asm volatile("cp.async.commit_group;"); }
__device__ __forceinline__ void cp_wait0()  { asm volatile("cp.async.wait_group 0;"); }
__device__ __forceinline__ void cp_wait1()  { asm volatile("cp.async.wait_group 1;"); }

__device__ __forceinline__ uint32_t pack_bf16x2(float lo, float hi) {
    uint32_t r;
    asm("cvt.rn.bf16x2.f32 %0, %1, %2;" : "=r"(r) : "f"(hi), "f"(lo));
    return r;
}

// ---------------- setup kernels ----------------
__global__ void convert_w(const float* __restrict__ qkv_w, const float* __restrict__ proj_w,
                          const float* __restrict__ fc1_w, const float* __restrict__ fc2_w,
                          bf16* __restrict__ wb)
{
    int i = blockIdx.x * 256 + threadIdx.x;
    if (i >= W_TOT) return;
    float v;
    if      (i < W_PROJ) v = qkv_w[i - W_QKV];
    else if (i < W_FC1)  v = proj_w[i - W_PROJ];
    else if (i < W_FC2)  v = fc1_w[i - W_FC1];
    else                 v = fc2_w[i - W_FC2];
    wb[i] = __float2bfloat16(v);
}

__global__ void build_bm(const float* __restrict__ relb, const float* __restrict__ mask,
                         float* __restrict__ bm)
{
    int idx = blockIdx.x * 256 + threadIdx.x;
    if (idx >= BM_ELEMS) return;
    int c   = idx % 56;
    int tmp = idx / 56;
    int r   = tmp % 49;  tmp /= 49;
    int h   = tmp % 3;
    int wi  = tmp / 3;
    float v;
    if (c < 49) {
        int i1 = r / WS, j1 = r % WS, i2 = c / WS, j2 = c % WS;
        int ridx = (i1 - i2 + WS - 1) * (2 * WS - 1) + (j1 - j2 + WS - 1);
        v = relb[ridx * NHEADS + h] + mask[(size_t)wi * (NWIN * NWIN) + r * NWIN + c];
    } else {
        v = -1e9f;
    }
    bm[idx] = v;
}

// ---------------- LayerNorm (warp per token), bf16 output ----------------
template<int MODE>
__global__ __launch_bounds__(256)
void ln_kernel(const float* __restrict__ x, const float* __restrict__ g,
               const float* __restrict__ beta, bf16* __restrict__ out)
{
    int t    = (blockIdx.x * blockDim.x + threadIdx.x) >> 5;
    int lane = threadIdx.x & 31;
    if (t >= M_TOK) return;

    const float* src;
    if (MODE == 0) {
        int win = t / NWIN, n = t % NWIN;
        int b  = win >> 8;
        int wi = win & 255;
        int wh = wi >> 4, ww = wi & 15;
        int i = n / WS, j = n % WS;
        int r = wh * WS + i + SHIFT; if (r >= HH)   r -= HH;
        int c = ww * WS + j + SHIFT; if (c >= WWID) c -= WWID;
        src = x + ((size_t)b * (HH * WWID) + r * WWID + c) * CC;
    } else {
        src = x + (size_t)t * CC;
    }

    float v0 = src[lane], v1 = src[lane + 32], v2 = src[lane + 64];
    float s = v0 + v1 + v2;
    #pragma unroll
    for (int o = 16; o; o >>= 1) s += __shfl_xor_sync(0xffffffffu, s, o);
    float mean = s * (1.0f / 96.0f);
    float d0 = v0 - mean, d1 = v1 - mean, d2 = v2 - mean;
    float q = d0 * d0 + d1 * d1 + d2 * d2;
    #pragma unroll
    for (int o = 16; o; o >>= 1) q += __shfl_xor_sync(0xffffffffu, q, o);
    float rstd = rsqrtf(q * (1.0f / 96.0f) + 1e-5f);

    bf16* dst = out + (size_t)t * CC;
    dst[lane]      = __float2bfloat16(d0 * rstd * g[lane]      + beta[lane]);
    dst[lane + 32] = __float2bfloat16(d1 * rstd * g[lane + 32] + beta[lane + 32]);
    dst[lane + 64] = __float2bfloat16(d2 * rstd * g[lane + 64] + beta[lane + 64]);
}

// ---------------- bf16 TC GEMM, K = KTILES*96 -------------------------------
// BM=128, BN=96, 384 threads (12 warps: 4m x 3n), warp tile 32x32.
// KTILES==1: single-shot stage, one sync, 6 unrolled k-chunks.
// KTILES>1:  double-buffered BK=96 pipeline.
template<int KTILES, int EPI, typename OUTT>
__global__ __launch_bounds__(384)
void gemm_tc(const bf16* __restrict__ A, const bf16* __restrict__ W,
             const float* __restrict__ bias, OUTT* __restrict__ out,
             const float* __restrict__ res, int N)
{
    constexpr int K    = KTILES * 96;
    constexpr int NBUF = (KTILES > 1) ? 2 : 1;
    constexpr int ABUF = 128 * SSTR;          // elems per A buffer
    constexpr int WBUF = 96 * SSTR;

    extern __shared__ bf16 smem[];
    bf16* As = smem;                          // [NBUF][128][SSTR]
    bf16* Ws = smem + NBUF * ABUF;            // [NBUF][96][SSTR]

    int tid  = threadIdx.x;
    int wid  = tid >> 5, lane = tid & 31;
    int g    = lane >> 2, t = lane & 3;
    int wm   = wid & 3, wn = wid >> 2;
    int m0   = blockIdx.x * 128, n0 = blockIdx.y * 96;

    uint32_t as_base = (uint32_t)__cvta_generic_to_shared(As);
    uint32_t ws_base = (uint32_t)__cvta_generic_to_shared(Ws);

    int lrow = lane & 7, lsel = lane >> 3;
    int ra = (lsel & 1) * 8 + lrow;
    int caoff = (lsel >> 1) * 8;

    float c[2][4][4];
    #pragma unroll
    for (int i = 0; i < 2; i++)
        #pragma unroll
        for (int j = 0; j < 4; j++)
            #pragma unroll
            for (int l = 0; l < 4; l++) c[i][j][l] = 0.f;

    // stage one 96-wide k-tile (A: 128x96, W: 96x96) via cp.async
    auto stage = [&](int buf, int kt) {
        #pragma unroll
        for (int i = 0; i < 4; i++) {            // A: 1536 chunks / 384
            int idx = tid + i * 384;
            int row = idx / 12, ch = idx % 12;
            cp16(as_base + (buf * ABUF + row * SSTR + ch * 8) * 2,
                 A + (size_t)(m0 + row) * K + kt * 96 + ch * 8);
        }
        #pragma unroll
        for (int i = 0; i < 3; i++) {            // W: 1152 chunks / 384
            int idx = tid + i * 384;
            int row = idx / 12, ch = idx % 12;
            cp16(ws_base + (buf * WBUF + row * SSTR + ch * 8) * 2,
                 W + (size_t)(n0 + row) * K + kt * 96 + ch * 8);
        }
    };

    stage(0, 0);
    cp_commit();

    #pragma unroll
    for (int kt = 0; kt < KTILES; kt++) {
        int buf = kt & 1;
        if (KTILES > 1 && kt + 1 < KTILES) {
            stage((kt + 1) & 1, kt + 1);
            cp_commit();
            cp_wait1();
        } else {
            cp_wait0();
        }
        __syncthreads();

        #pragma unroll
        for (int kk = 0; kk < 6; kk++) {
            int kc = kk * 16 + caoff;
            uint32_t a[2][4];
            #pragma unroll
            for (int mt = 0; mt < 2; mt++) {
                int row = wm * 32 + mt * 16 + ra;
                ldsm4(a[mt][0], a[mt][1], a[mt][2], a[mt][3],
                      as_base + (buf * ABUF + row * SSTR + kc) * 2);
            }
            uint32_t b[2][4];
            #pragma unroll
            for (int np = 0; np < 2; np++) {
                int row = wn * 32 + np * 16 + ra;
                ldsm4(b[np][0], b[np][1], b[np][2], b[np][3],
                      ws_base + (buf * WBUF + row * SSTR + kc) * 2);
            }
            #pragma unroll
            for (int nt = 0; nt < 4; nt++) {
                uint32_t b0 = b[nt >> 1][nt & 1];
                uint32_t b1 = b[nt >> 1][(nt & 1) + 2];
                #pragma unroll
                for (int mt = 0; mt < 2; mt++)
                    mma_bf16(c[mt][nt], a[mt][0], a[mt][1], a[mt][2], a[mt][3], b0, b1);
            }
        }
        if (KTILES > 1 && kt + 1 < KTILES) __syncthreads();
    }

    #pragma unroll
    for (int mt = 0; mt < 2; mt++) {
        #pragma unroll
        for (int rh = 0; rh < 2; rh++) {
            int m = m0 + wm * 32 + mt * 16 + g + rh * 8;
            size_t rowbase;
            if (EPI == 2) {
                int win = m / NWIN, nn = m % NWIN;
                int b  = win >> 8;
                int wi = win & 255;
                int wh = wi >> 4, ww = wi & 15;
                int ii = nn / WS, jj = nn % WS;
                int r = wh * WS + ii + SHIFT; if (r >= HH)   r -= HH;
                int ccol = ww * WS + jj + SHIFT; if (ccol >= WWID) ccol -= WWID;
                rowbase = ((size_t)b * (HH * WWID) + r * WWID + ccol) * CC;
            } else {
                rowbase = (size_t)m * N;
            }
            #pragma unroll
            for (int nt = 0; nt < 4; nt++) {
                #pragma unroll
                for (int j = 0; j < 2; j++) {
                    int n = n0 + wn * 32 + nt * 8 + 2 * t + j;
                    float v = c[mt][nt][rh * 2 + j] + bias[n];
                    if (EPI == 0) {
                        out[rowbase + n] = (OUTT)__float2bfloat16(v);
                    } else if (EPI == 1) {
                        float gl = 0.5f * v * (1.0f + erff(v * 0.70710678118654752f));
                        out[rowbase + n] = (OUTT)__float2bfloat16(gl);
                    } else {
                        out[rowbase + n] = (OUTT)(res[rowbase + n] + v);
                    }
                }
            }
        }
    }
}

// ---------------- attention: register softmax, P-in-register PV ------------
__global__ __launch_bounds__(128)
void attn_tc(const bf16* __restrict__ qkv, const float* __restrict__ bm,
             bf16* __restrict__ out)
{
    __shared__ bf16 qs [64][40];
    __shared__ bf16 ks_[56][40];
    __shared__ bf16 vt [32][72];

    int win  = blockIdx.x;
    int tid  = threadIdx.x;
    int wid  = tid >> 5, lane = tid & 31;
    int g    = lane >> 2, t = lane & 3;
    const float scale = 0.17677669529663689f;

    const bf16* base = qkv + (size_t)win * NWIN * (3 * CC);
    int r0 = wid * 16 + g, r1 = r0 + 8;
    bool v0ok = r0 < NWIN, v1ok = r1 < NWIN;

    for (int h = 0; h < NHEADS; h++) {
        for (int p = tid; p < 64 * HD; p += 128) {
            int n = p >> 5, d = p & 31;
            qs[n][d] = (n < NWIN) ? base[(size_t)n * (3 * CC) + h * HD + d] : (bf16)0.f;
        }
        for (int p = tid; p < 64 * HD; p += 128) {
            int n = p >> 5, d = p & 31;
            bf16 kv = (n < NWIN) ? base[(size_t)n * (3 * CC) + CC + h * HD + d] : (bf16)0.f;
            bf16 vv = (n < NWIN) ? base[(size_t)n * (3 * CC) + 2 * CC + h * HD + d] : (bf16)0.f;
            if (n < 56) ks_[n][d] = kv;
            vt[d][n] = vv;
        }
        __syncthreads();

        float sc[7][4];
        #pragma unroll
        for (int nt = 0; nt < 7; nt++)
            #pragma unroll
            for (int l = 0; l < 4; l++) sc[nt][l] = 0.f;

        #pragma unroll
        for (int ks = 0; ks < 2; ks++) {
            int kc = ks * 16 + 2 * t;
            uint32_t a0 = *(const uint32_t*)&qs[r0][kc];
            uint32_t a1 = *(const uint32_t*)&qs[r1][kc];
            uint32_t a2 = *(const uint32_t*)&qs[r0][kc + 8];
            uint32_t a3 = *(const uint32_t*)&qs[r1][kc + 8];
            #pragma unroll
            for (int nt = 0; nt < 7; nt++) {
                int nr = nt * 8 + g;
                uint32_t b0 = *(const uint32_t*)&ks_[nr][kc];
                uint32_t b1 = *(const uint32_t*)&ks_[nr][kc + 8];
                mma_bf16(sc[nt], a0, a1, a2, a3, b0, b1);
            }
        }

        const float* bmh = bm + ((size_t)((win & 255) * 3 + h)) * (49 * 56);
        #pragma unroll
        for (int nt = 0; nt < 7; nt++) {
            int cbase = nt * 8 + 2 * t;
            #pragma unroll
            for (int j = 0; j < 2; j++) {
                sc[nt][j]     = v0ok ? sc[nt][j]     * scale + bmh[r0 * 56 + cbase + j] : 0.f;
                sc[nt][2 + j] = v1ok ? sc[nt][2 + j] * scale + bmh[r1 * 56 + cbase + j] : 0.f;
            }
        }

        float mx0 = -1e30f, mx1 = -1e30f;
        #pragma unroll
        for (int nt = 0; nt < 7; nt++) {
            mx0 = fmaxf(mx0, fmaxf(sc[nt][0], sc[nt][1]));
            mx1 = fmaxf(mx1, fmaxf(sc[nt][2], sc[nt][3]));
        }
        #pragma unroll
        for (int o = 1; o <= 2; o <<= 1) {
            mx0 = fmaxf(mx0, __shfl_xor_sync(0xffffffffu, mx0, o));
            mx1 = fmaxf(mx1, __shfl_xor_sync(0xffffffffu, mx1, o));
        }
        float sum0 = 0.f, sum1 = 0.f;
        #pragma unroll
        for (int nt = 0; nt < 7; nt++) {
            sc[nt][0] = __expf(sc[nt][0] - mx0); sum0 += sc[nt][0];
            sc[nt][1] = __expf(sc[nt][1] - mx0); sum0 += sc[nt][1];
            sc[nt][2] = __expf(sc[nt][2] - mx1); sum1 += sc[nt][2];
            sc[nt][3] = __expf(sc[nt][3] - mx1); sum1 += sc[nt][3];
        }
        #pragma unroll
        for (int o = 1; o <= 2; o <<= 1) {
            sum0 += __shfl_xor_sync(0xffffffffu, sum0, o);
            sum1 += __shfl_xor_sync(0xffffffffu, sum1, o);
        }
        float inv0 = 1.0f / sum0, inv1 = 1.0f / sum1;
        #pragma unroll
        for (int nt = 0; nt < 7; nt++) {
            sc[nt][0] *= inv0; sc[nt][1] *= inv0;
            sc[nt][2] *= inv1; sc[nt][3] *= inv1;
        }

        float oc[4][4];
        #pragma unroll
        for (int nt = 0; nt < 4; nt++)
            #pragma unroll
            for (int l = 0; l < 4; l++) oc[nt][l] = 0.f;

        #pragma unroll
        for (int ks = 0; ks < 4; ks++) {
            uint32_t a0 = pack_bf16x2(sc[2 * ks][0], sc[2 * ks][1]);
            uint32_t a1 = pack_bf16x2(sc[2 * ks][2], sc[2 * ks][3]);
            uint32_t a2 = 0, a3 = 0;
            if (ks < 3) {
                a2 = pack_bf16x2(sc[2 * ks + 1][0], sc[2 * ks + 1][1]);
                a3 = pack_bf16x2(sc[2 * ks + 1][2], sc[2 * ks + 1][3]);
            }
            int kc = ks * 16 + 2 * t;
            #pragma unroll
            for (int nt = 0; nt < 4; nt++) {
                int nr = nt * 8 + g;
                uint32_t b0 = *(const uint32_t*)&vt[nr][kc];
                uint32_t b1 = *(const uint32_t*)&vt[nr][kc + 8];
                mma_bf16(oc[nt], a0, a1, a2, a3, b0, b1);
            }
        }

        #pragma unroll
        for (int nt = 0; nt < 4; nt++) {
            #pragma unroll
            for (int j = 0; j < 2; j++) {
                int d = nt * 8 + 2 * t + j;
                if (v0ok)
                    out[((size_t)win * NWIN + r0) * CC + h * HD + d] =
                        __float2bfloat16(oc[nt][j]);
                if (v1ok)
                    out[((size_t)win * NWIN + r1) * CC + h * HD + d] =
                        __float2bfloat16(oc[nt][2 + j]);
            }
        }
        __syncthreads();
    }
}

// ---------------- launch ----------------
extern "C" void kernel_launch(void* const* d_in, const int* in_sizes, int n_in,
                              void* d_out, int out_size)
{
    const float* x      = (const float*)d_in[0];
    const float* mask   = (const float*)d_in[1];
    const float* n1g    = (const float*)d_in[2];
    const float* n1b    = (const float*)d_in[3];
    const float* qkv_w  = (const float*)d_in[4];
    const float* qkv_b  = (const float*)d_in[5];
    const float* relb   = (const float*)d_in[6];
    const float* proj_w = (const float*)d_in[7];
    const float* proj_b = (const float*)d_in[8];
    const float* n2g    = (const float*)d_in[9];
    const float* n2b    = (const float*)d_in[10];
    const float* fc1_w  = (const float*)d_in[11];
    const float* fc1_b  = (const float*)d_in[12];
    const float* fc2_w  = (const float*)d_in[13];
    const float* fc2_b  = (const float*)d_in[14];
    float* out = (float*)d_out;

    bf16 *xw, *qkvb, *att, *y, *h1, *wb;
    float *x1, *bm;
    cudaGetSymbolAddress((void**)&xw,   g_xw);
    cudaGetSymbolAddress((void**)&qkvb, g_qkv);
    cudaGetSymbolAddress((void**)&att,  g_att);
    cudaGetSymbolAddress((void**)&x1,   g_x1);
    cudaGetSymbolAddress((void**)&y,    g_y);
    cudaGetSymbolAddress((void**)&h1,   g_h1);
    cudaGetSymbolAddress((void**)&wb,   g_wb);
    cudaGetSymbolAddress((void**)&bm,   g_bm);

    const int LN_BLOCKS = M_TOK / 8;
    const int GM = M_TOK / 128;         // 1568

    const int SM1 = (128 + 96) * SSTR * 2;       // 46592 B  (KTILES=1)
    const int SM4 = 2 * (128 + 96) * SSTR * 2;   // 93184 B  (KTILES=4)

    cudaFuncSetAttribute((const void*)gemm_tc<1, 0, bf16>,
                         cudaFuncAttributeMaxDynamicSharedMemorySize, SM1);
    cudaFuncSetAttribute((const void*)gemm_tc<1, 2, float>,
                         cudaFuncAttributeMaxDynamicSharedMemorySize, SM1);
    cudaFuncSetAttribute((const void*)gemm_tc<1, 1, bf16>,
                         cudaFuncAttributeMaxDynamicSharedMemorySize, SM1);
    cudaFuncSetAttribute((const void*)gemm_tc<4, 3, float>,
                         cudaFuncAttributeMaxDynamicSharedMemorySize, SM4);

    convert_w<<<(W_TOT + 255) / 256, 256>>>(qkv_w, proj_w, fc1_w, fc2_w, wb);
    build_bm<<<(BM_ELEMS + 255) / 256, 256>>>(relb, mask, bm);
    ln_kernel<0><<<LN_BLOCKS, 256>>>(x, n1g, n1b, xw);
    gemm_tc<1, 0, bf16><<<dim3(GM, 3), 384, SM1>>>(xw, wb + W_QKV, qkv_b, qkvb, nullptr, 3 * CC);
    attn_tc<<<BB * NW_IMG, 128>>>(qkvb, bm, att);
    gemm_tc<1, 2, float><<<dim3(GM, 1), 384, SM1>>>(att, wb + W_PROJ, proj_b, x1, x, CC);
    ln_kernel<1><<<LN_BLOCKS, 256>>>(x1, n2g, n2b, y);
    gemm_tc<1, 1, bf16><<<dim3(GM, 4), 384, SM1>>>(y, wb + W_FC1, fc1_b, h1, nullptr, HID_D);
    gemm_tc<4, 3, float><<<dim3(GM, 1), 384, SM4>>>(h1, wb + W_FC2, fc2_b, out, x1, CC);
}